// round 8
// baseline (speedup 1.0000x reference)
#include <cuda_runtime.h>
#include <cuda_bf16.h>
#include <math.h>
#include <stdint.h>

// Problem constants
#define Bq   4
#define Sq   2048
#define Dm   1024
#define Hh   16
#define HDm  64
#define DFm  4096
#define NTOK (Bq*Sq)   // 8192
#define QKV_SZ (NTOK*Dm)   // = BH * S * 64

// ---------------------------------------------------------------------------
// Scratch (module-load allocated)
// ---------------------------------------------------------------------------
__device__ float g_x2 [NTOK*Dm];

__device__ __nv_bfloat16 g_ahi[NTOK*Dm];
__device__ __nv_bfloat16 g_alo[NTOK*Dm];
__device__ __nv_bfloat16 g_hhi[NTOK*DFm];
__device__ __nv_bfloat16 g_hlo[NTOK*DFm];

__device__ __nv_bfloat16 g_qh[QKV_SZ], g_ql[QKV_SZ];
__device__ __nv_bfloat16 g_kh[QKV_SZ], g_kl[QKV_SZ];
__device__ __nv_bfloat16 g_vh[QKV_SZ], g_vl[QKV_SZ];

__device__ __nv_bfloat16 g_wqh[Dm*Dm],  g_wql[Dm*Dm];
__device__ __nv_bfloat16 g_wkh[Dm*Dm],  g_wkl[Dm*Dm];
__device__ __nv_bfloat16 g_wvh[Dm*Dm],  g_wvl[Dm*Dm];
__device__ __nv_bfloat16 g_woh[Dm*Dm],  g_wol[Dm*Dm];
__device__ __nv_bfloat16 g_w1h[Dm*DFm], g_w1l[Dm*DFm];
__device__ __nv_bfloat16 g_w2h[Dm*DFm], g_w2l[Dm*DFm];

// ---------------------------------------------------------------------------
// PTX helpers (base-target safe: cp.async + ldmatrix + mma.sync only)
// ---------------------------------------------------------------------------
__device__ __forceinline__ uint32_t s2u(const void* p) {
    uint32_t a;
    asm("{ .reg .u64 t; cvta.to.shared.u64 t, %1; cvt.u32.u64 %0, t; }"
        : "=r"(a) : "l"(p));
    return a;
}
__device__ __forceinline__ void cpa16(uint32_t d, const void* s) {
    asm volatile("cp.async.cg.shared.global [%0], [%1], 16;"
                 :: "r"(d), "l"(s) : "memory");
}
__device__ __forceinline__ void cpa_commit() {
    asm volatile("cp.async.commit_group;" ::: "memory");
}
template<int NN> __device__ __forceinline__ void cpa_wait() {
    asm volatile("cp.async.wait_group %0;" :: "n"(NN) : "memory");
}
__device__ __forceinline__ void ldsm4(uint32_t* r, uint32_t a) {
    asm volatile("ldmatrix.sync.aligned.m8n8.x4.shared.b16 {%0,%1,%2,%3}, [%4];"
                 : "=r"(r[0]), "=r"(r[1]), "=r"(r[2]), "=r"(r[3]) : "r"(a));
}
__device__ __forceinline__ void ldsm4t(uint32_t* r, uint32_t a) {
    asm volatile("ldmatrix.sync.aligned.m8n8.x4.trans.shared.b16 {%0,%1,%2,%3}, [%4];"
                 : "=r"(r[0]), "=r"(r[1]), "=r"(r[2]), "=r"(r[3]) : "r"(a));
}
__device__ __forceinline__ void mma_bf16(float* d, const uint32_t* a, const uint32_t* b) {
    asm volatile(
        "mma.sync.aligned.m16n8k16.row.col.f32.bf16.bf16.f32 "
        "{%0,%1,%2,%3}, {%4,%5,%6,%7}, {%8,%9}, {%0,%1,%2,%3};"
        : "+f"(d[0]), "+f"(d[1]), "+f"(d[2]), "+f"(d[3])
        : "r"(a[0]), "r"(a[1]), "r"(a[2]), "r"(a[3]), "r"(b[0]), "r"(b[1]));
}

// split fp32 pairs into bf16 hi/lo
__device__ __forceinline__ void split_pack2(float x, float y, uint32_t& H, uint32_t& L) {
    __nv_bfloat16 hx = __float2bfloat16(x), hy = __float2bfloat16(y);
    float lx = x - __bfloat162float(hx), ly = y - __bfloat162float(hy);
    __nv_bfloat16 gx = __float2bfloat16(lx), gy = __float2bfloat16(ly);
    H = (uint32_t)__bfloat16_as_ushort(hx) | ((uint32_t)__bfloat16_as_ushort(hy) << 16);
    L = (uint32_t)__bfloat16_as_ushort(gx) | ((uint32_t)__bfloat16_as_ushort(gy) << 16);
}
__device__ __forceinline__ void split_store2(float x, float y,
                                             __nv_bfloat16* hi, __nv_bfloat16* lo) {
    uint32_t H, L;
    split_pack2(x, y, H, L);
    *(uint32_t*)hi = H;
    *(uint32_t*)lo = L;
}
__device__ __forceinline__ void split_store4(float4 v, __nv_bfloat16* hi, __nv_bfloat16* lo) {
    split_store2(v.x, v.y, hi,     lo);
    split_store2(v.z, v.w, hi + 2, lo + 2);
}

#define SWZ(x) ((x) ^ (((x) >> 3) & 0x70))

// ---------------------------------------------------------------------------
// LayerNorm: one block per row, emits bf16 hi/lo split directly
// ---------------------------------------------------------------------------
__global__ __launch_bounds__(256)
void ln_kernel(const float* __restrict__ X, const float* __restrict__ G,
               const float* __restrict__ Bt,
               __nv_bfloat16* __restrict__ Yhi, __nv_bfloat16* __restrict__ Ylo)
{
    __shared__ float ss[8], sq[8];
    const int r = blockIdx.x, tid = threadIdx.x;
    const float* xr = X + (size_t)r * Dm;
    float4 v = *(const float4*)(xr + tid * 4);
    float s = v.x + v.y + v.z + v.w;
    float q = v.x*v.x + v.y*v.y + v.z*v.z + v.w*v.w;
#pragma unroll
    for (int off = 16; off >= 1; off >>= 1) {
        s += __shfl_xor_sync(0xffffffffu, s, off);
        q += __shfl_xor_sync(0xffffffffu, q, off);
    }
    if ((tid & 31) == 0) { ss[tid >> 5] = s; sq[tid >> 5] = q; }
    __syncthreads();
    float ts = 0.f, tq = 0.f;
#pragma unroll
    for (int w = 0; w < 8; w++) { ts += ss[w]; tq += sq[w]; }
    const float mu   = ts * (1.0f / Dm);
    const float var  = tq * (1.0f / Dm) - mu * mu;
    const float rstd = rsqrtf(var + 1e-5f);
    float4 g4 = *(const float4*)(G  + tid * 4);
    float4 b4 = *(const float4*)(Bt + tid * 4);
    float4 o;
    o.x = (v.x - mu) * rstd * g4.x + b4.x;
    o.y = (v.y - mu) * rstd * g4.y + b4.y;
    o.z = (v.z - mu) * rstd * g4.z + b4.z;
    o.w = (v.w - mu) * rstd * g4.w + b4.w;
    const size_t idx = (size_t)r * Dm + tid * 4;
    split_store4(o, Yhi + idx, Ylo + idx);
}

// ---------------------------------------------------------------------------
// Weight convert+transpose: W[K,N] f32 -> WT hi/lo [N,K] bf16
// ---------------------------------------------------------------------------
__global__ __launch_bounds__(256)
void wconv_kernel(const float* __restrict__ W, __nv_bfloat16* __restrict__ Th,
                  __nv_bfloat16* __restrict__ Tl, int K, int N)
{
    __shared__ float t[32][33];
    const int n0 = blockIdx.x * 32, k0 = blockIdx.y * 32;
    const int tx = threadIdx.x, ty = threadIdx.y;
#pragma unroll
    for (int i = 0; i < 4; i++)
        t[ty + i*8][tx] = W[(size_t)(k0 + ty + i*8) * N + n0 + tx];
    __syncthreads();
#pragma unroll
    for (int i = 0; i < 4; i++) {
        const int r = ty + i*8;
        float v = t[tx][r];                     // = W[k0+tx][n0+r]
        size_t o = (size_t)(n0 + r) * K + k0 + tx;
        __nv_bfloat16 h = __float2bfloat16(v);
        Th[o] = h;
        Tl[o] = __float2bfloat16(v - __bfloat162float(h));
    }
}

// ---------------------------------------------------------------------------
// HMMA split-bf16 GEMM: C[M,N] = A[M,K] @ W[K,N] + bias (+epilogue)
// CTA tile 128x256, K-chunk 64, 2-stage cp.async pipeline.
// 8 warps as 2(M)x4(N); warp tile 64x64. B frags via ldsm4 (2 per issue).
// MODE: 1 = bias+GELU -> bf16 hi/lo, 2 = bias+residual -> f32,
//       3 = bias -> bf16 hi/lo scatter to [B,H,S,64]
// ---------------------------------------------------------------------------
#define TMq 128
#define TNq 256
#define A_TILE_B 16384               // 128 x 128B
#define B_TILE_B 32768               // 256 x 128B
#define STG_BYTES (2*A_TILE_B + 2*B_TILE_B)   // 98304
#define GEMM_SMEM (2*STG_BYTES)               // 196608
#define OFF_AL (A_TILE_B)
#define OFF_BH (2*A_TILE_B)
#define OFF_BL (2*A_TILE_B + B_TILE_B)

__device__ __forceinline__ void load_stage(
    uint32_t st,
    const __nv_bfloat16* __restrict__ Ahi, const __nv_bfloat16* __restrict__ Alo,
    const __nv_bfloat16* __restrict__ Bhi, const __nv_bfloat16* __restrict__ Blo,
    int m0, int n0, int kc, int K, int tid)
{
#pragma unroll
    for (int j = 0; j < 4; j++) {          // A: 128 rows x 8 chunks of 16B
        const int i = tid + j * 256;
        const int r = i >> 3, c = i & 7;
        const uint32_t off = SWZ((uint32_t)(r * 128 + c * 16));
        const size_t ga = (size_t)(m0 + r) * K + kc + c * 8;
        cpa16(st + off,          Ahi + ga);
        cpa16(st + OFF_AL + off, Alo + ga);
    }
#pragma unroll
    for (int j = 0; j < 8; j++) {          // B: 256 rows x 8 chunks of 16B
        const int i = tid + j * 256;
        const int r = i >> 3, c = i & 7;
        const uint32_t off = SWZ((uint32_t)(r * 128 + c * 16));
        const size_t gb = (size_t)(n0 + r) * K + kc + c * 8;
        cpa16(st + OFF_BH + off, Bhi + gb);
        cpa16(st + OFF_BL + off, Blo + gb);
    }
}

template<int MODE>
__global__ __launch_bounds__(256, 1)
void gemm_hmma(const __nv_bfloat16* __restrict__ Ahi, const __nv_bfloat16* __restrict__ Alo,
               const __nv_bfloat16* __restrict__ Bhi, const __nv_bfloat16* __restrict__ Blo,
               const float* __restrict__ bias, const float* __restrict__ res,
               float* __restrict__ Cf,
               __nv_bfloat16* __restrict__ Chi, __nv_bfloat16* __restrict__ Clo,
               int N, int K)
{
    extern __shared__ __align__(1024) char smem[];
    const uint32_t sb = s2u(smem);
    const int tid = threadIdx.x, lane = tid & 31, warp = tid >> 5;
    const int wm = warp >> 2, wn = warp & 3;       // 2(M) x 4(N)
    const int m0 = blockIdx.y * TMq, n0 = blockIdx.x * TNq;

    float acc[4][8][4];
#pragma unroll
    for (int a = 0; a < 4; a++)
#pragma unroll
        for (int b = 0; b < 8; b++)
#pragma unroll
            for (int c = 0; c < 4; c++) acc[a][b][c] = 0.f;

    // ldmatrix base byte offsets
    uint32_t rowA[4], rowB[4];
#pragma unroll
    for (int mf = 0; mf < 4; mf++)
        rowA[mf] = (uint32_t)((wm*64 + mf*16 + (lane & 15)) * 128 + (lane >> 4) * 16);
#pragma unroll
    for (int nfp = 0; nfp < 4; nfp++)
        rowB[nfp] = (uint32_t)((wn*64 + nfp*16 + ((lane >> 4) << 3) + (lane & 7)) * 128
                               + ((lane >> 3) & 1) * 16);

    const int NC = K >> 6;
    load_stage(sb,             Ahi, Alo, Bhi, Blo, m0, n0, 0,  K, tid); cpa_commit();
    load_stage(sb + STG_BYTES, Ahi, Alo, Bhi, Blo, m0, n0, 64, K, tid); cpa_commit();

    for (int c = 0; c < NC; c++) {
        if (c + 1 < NC) cpa_wait<1>(); else cpa_wait<0>();
        __syncthreads();

        const uint32_t stA = sb + (c & 1) * STG_BYTES;
#pragma unroll
        for (int ks = 0; ks < 4; ks++) {
            const uint32_t ko = ks * 32;
            uint32_t ah[4][4], al[4][4], bh[4][4], bl[4][4];
#pragma unroll
            for (int mf = 0; mf < 4; mf++) {
                const uint32_t so = SWZ(rowA[mf] + ko);
                ldsm4(ah[mf], stA + so);
                ldsm4(al[mf], stA + OFF_AL + so);
            }
#pragma unroll
            for (int nfp = 0; nfp < 4; nfp++) {
                const uint32_t so = SWZ(rowB[nfp] + ko);
                ldsm4(bh[nfp], stA + OFF_BH + so);
                ldsm4(bl[nfp], stA + OFF_BL + so);
            }
#pragma unroll
            for (int mf = 0; mf < 4; mf++)
#pragma unroll
                for (int nfp = 0; nfp < 4; nfp++) {
                    mma_bf16(acc[mf][2*nfp],   ah[mf], &bh[nfp][0]);
                    mma_bf16(acc[mf][2*nfp],   ah[mf], &bl[nfp][0]);
                    mma_bf16(acc[mf][2*nfp],   al[mf], &bh[nfp][0]);
                    mma_bf16(acc[mf][2*nfp+1], ah[mf], &bh[nfp][2]);
                    mma_bf16(acc[mf][2*nfp+1], ah[mf], &bl[nfp][2]);
                    mma_bf16(acc[mf][2*nfp+1], al[mf], &bh[nfp][2]);
                }
        }
        __syncthreads();
        if (c + 2 < NC) {
            load_stage(stA, Ahi, Alo, Bhi, Blo, m0, n0, (c + 2) * 64, K, tid);
            cpa_commit();
        }
    }

    const int qr = lane >> 2, qc = (lane & 3) * 2;
#pragma unroll
    for (int mf = 0; mf < 4; mf++) {
#pragma unroll
        for (int nf = 0; nf < 8; nf++) {
            const int row = m0 + wm*64 + mf*16 + qr;
            const int col = n0 + wn*64 + nf*8 + qc;
            float2 bv = *(const float2*)(bias + col);
            float x0 = acc[mf][nf][0] + bv.x, x1 = acc[mf][nf][1] + bv.y;
            float y0 = acc[mf][nf][2] + bv.x, y1 = acc[mf][nf][3] + bv.y;
            if (MODE == 1) {
                x0 *= normcdff(x0); x1 *= normcdff(x1);
                y0 *= normcdff(y0); y1 *= normcdff(y1);
                const size_t o0 = (size_t)row * N + col;
                const size_t o1 = (size_t)(row + 8) * N + col;
                split_store2(x0, x1, Chi + o0, Clo + o0);
                split_store2(y0, y1, Chi + o1, Clo + o1);
            } else if (MODE == 2) {
                const size_t o0 = (size_t)row * N + col;
                const size_t o1 = (size_t)(row + 8) * N + col;
                float2 r0 = *(const float2*)(res + o0);
                float2 r1 = *(const float2*)(res + o1);
                *(float2*)(Cf + o0) = make_float2(x0 + r0.x, x1 + r0.y);
                *(float2*)(Cf + o1) = make_float2(y0 + r1.x, y1 + r1.y);
            } else {
                // scatter to [B,H,S,64] as bf16 hi/lo
                const int h = col >> 6, hd = col & 63;
                const int b0r = row >> 11, s0 = row & 2047;
                const int b1r = (row + 8) >> 11, s1 = (row + 8) & 2047;
                const size_t o0 = ((size_t)(b0r * Hh + h) * Sq + s0) * HDm + hd;
                const size_t o1 = ((size_t)(b1r * Hh + h) * Sq + s1) * HDm + hd;
                split_store2(x0, x1, Chi + o0, Clo + o0);
                split_store2(y0, y1, Chi + o1, Clo + o1);
            }
        }
    }
}

// ---------------------------------------------------------------------------
// HMMA flash attention with split-bf16 QK^T and PV (unchanged from R7).
// ---------------------------------------------------------------------------
#define ATT_QB   16384                    // one Q tensor tile (128 x 128B)
#define ATT_KVB  8192                     // one KV tensor tile (64 x 128B)
#define ATT_STG  (4*ATT_KVB)              // kh, kl, vh, vl
#define ATT_SMEM (2*ATT_QB + 3*ATT_STG)   // 131072

__device__ __forceinline__ void att_load_stage(
    uint32_t st, const __nv_bfloat16* __restrict__ Kh, const __nv_bfloat16* __restrict__ Kl,
    const __nv_bfloat16* __restrict__ Vh, const __nv_bfloat16* __restrict__ Vl,
    size_t tb, int kv0, int tid)
{
#pragma unroll
    for (int j = 0; j < 8; j++) {
        const int i = tid + j * 256;           // 0..2047
        const int t = i >> 9;                  // 0..3 : kh,kl,vh,vl
        const int r = (i >> 3) & 63;
        const int c = i & 7;
        const __nv_bfloat16* src = (t == 0) ? Kh : (t == 1) ? Kl : (t == 2) ? Vh : Vl;
        cpa16(st + t * ATT_KVB + SWZ((uint32_t)(r * 128 + c * 16)),
              src + tb + (size_t)(kv0 + r) * HDm + c * 8);
    }
}

__global__ __launch_bounds__(256, 1)
void attn_hmma(const __nv_bfloat16* __restrict__ Qh_, const __nv_bfloat16* __restrict__ Ql_,
               const __nv_bfloat16* __restrict__ Kh_, const __nv_bfloat16* __restrict__ Kl_,
               const __nv_bfloat16* __restrict__ Vh_, const __nv_bfloat16* __restrict__ Vl_,
               __nv_bfloat16* __restrict__ Ohi, __nv_bfloat16* __restrict__ Olo)
{
    extern __shared__ __align__(1024) char smem[];
    const uint32_t sb = s2u(smem);
    const int tid = threadIdx.x, lane = tid & 31, warp = tid >> 5;
    const int bh = blockIdx.y;
    const int q0 = blockIdx.x * 128;
    const size_t tb = (size_t)bh * Sq * HDm;

    att_load_stage(sb + 2*ATT_QB,             Kh_, Kl_, Vh_, Vl_, tb, 0,   tid); cpa_commit();
    att_load_stage(sb + 2*ATT_QB +   ATT_STG, Kh_, Kl_, Vh_, Vl_, tb, 64,  tid); cpa_commit();
    att_load_stage(sb + 2*ATT_QB + 2*ATT_STG, Kh_, Kl_, Vh_, Vl_, tb, 128, tid); cpa_commit();
#pragma unroll
    for (int j = 0; j < 8; j++) {
        const int i = tid + j * 256;           // 0..2047
        const int t = i >> 10;                 // 0..1 : qh, ql
        const int r = (i >> 3) & 127;
        const int c = i & 7;
        const __nv_bfloat16* src = t ? Ql_ : Qh_;
        cpa16(sb + t * ATT_QB + SWZ((uint32_t)(r * 128 + c * 16)),
              src + tb + (size_t)(q0 + r) * HDm + c * 8);
    }
    cpa_commit();
    cpa_wait<0>();
    __syncthreads();

    uint32_t qfh[4][4], qfl[4][4];
    {
        const uint32_t qrow = (uint32_t)((16*warp + (lane & 15)) * 128 + (lane >> 4) * 16);
#pragma unroll
        for (int kf = 0; kf < 4; kf++) {
            const uint32_t so = SWZ(qrow + kf * 32);
            ldsm4(qfh[kf], sb + so);
            ldsm4(qfl[kf], sb + ATT_QB + so);
        }
    }

    float acco[8][4];
#pragma unroll
    for (int nf = 0; nf < 8; nf++)
#pragma unroll
        for (int c = 0; c < 4; c++) acco[nf][c] = 0.f;
    float m0v = -1e30f, m1v = -1e30f, l0v = 0.f, l1v = 0.f;

    const int NT = Sq / 64;   // 32
    int stg = 0;
    for (int c = 0; c < NT; c++) {
        const int rem = NT - 1 - c;
        if (rem >= 2)      cpa_wait<2>();
        else if (rem == 1) cpa_wait<1>();
        else               cpa_wait<0>();
        __syncthreads();

        const uint32_t stb = sb + 2*ATT_QB + stg * ATT_STG;

        float accs[8][4];
#pragma unroll
        for (int nf = 0; nf < 8; nf++)
#pragma unroll
            for (int q4 = 0; q4 < 4; q4++) accs[nf][q4] = 0.f;

#pragma unroll
        for (int kf = 0; kf < 4; kf++) {
            uint32_t bhf[4][4], blf[4][4];
#pragma unroll
            for (int nfp = 0; nfp < 4; nfp++) {
                const uint32_t row = (uint32_t)(16*nfp + ((lane >> 4) << 3) + (lane & 7));
                const uint32_t kb  = (uint32_t)(kf * 32 + ((lane >> 3) & 1) * 16);
                const uint32_t so  = SWZ(row * 128 + kb);
                ldsm4(bhf[nfp], stb + so);
                ldsm4(blf[nfp], stb + ATT_KVB + so);
            }
#pragma unroll
            for (int nfp = 0; nfp < 4; nfp++) {
                mma_bf16(accs[2*nfp],   qfh[kf], &bhf[nfp][0]);
                mma_bf16(accs[2*nfp],   qfh[kf], &blf[nfp][0]);
                mma_bf16(accs[2*nfp],   qfl[kf], &bhf[nfp][0]);
                mma_bf16(accs[2*nfp+1], qfh[kf], &bhf[nfp][2]);
                mma_bf16(accs[2*nfp+1], qfh[kf], &blf[nfp][2]);
                mma_bf16(accs[2*nfp+1], qfl[kf], &bhf[nfp][2]);
            }
        }

        float mx0 = -1e30f, mx1 = -1e30f;
#pragma unroll
        for (int nf = 0; nf < 8; nf++) {
            mx0 = fmaxf(mx0, fmaxf(accs[nf][0], accs[nf][1]));
            mx1 = fmaxf(mx1, fmaxf(accs[nf][2], accs[nf][3]));
        }
        mx0 *= 0.125f; mx1 *= 0.125f;
#pragma unroll
        for (int off = 1; off <= 2; off <<= 1) {
            mx0 = fmaxf(mx0, __shfl_xor_sync(0xffffffffu, mx0, off));
            mx1 = fmaxf(mx1, __shfl_xor_sync(0xffffffffu, mx1, off));
        }
        const float mn0 = fmaxf(m0v, mx0), mn1 = fmaxf(m1v, mx1);
        const float cr0 = __expf(m0v - mn0), cr1 = __expf(m1v - mn1);
        float sum0 = 0.f, sum1 = 0.f;
#pragma unroll
        for (int nf = 0; nf < 8; nf++) {
            float p0 = __expf(fmaf(accs[nf][0], 0.125f, -mn0));
            float p1 = __expf(fmaf(accs[nf][1], 0.125f, -mn0));
            float p2 = __expf(fmaf(accs[nf][2], 0.125f, -mn1));
            float p3 = __expf(fmaf(accs[nf][3], 0.125f, -mn1));
            accs[nf][0] = p0; accs[nf][1] = p1; accs[nf][2] = p2; accs[nf][3] = p3;
            sum0 += p0 + p1; sum1 += p2 + p3;
        }
#pragma unroll
        for (int off = 1; off <= 2; off <<= 1) {
            sum0 += __shfl_xor_sync(0xffffffffu, sum0, off);
            sum1 += __shfl_xor_sync(0xffffffffu, sum1, off);
        }
        l0v = l0v * cr0 + sum0;  m0v = mn0;
        l1v = l1v * cr1 + sum1;  m1v = mn1;
#pragma unroll
        for (int nf = 0; nf < 8; nf++) {
            acco[nf][0] *= cr0; acco[nf][1] *= cr0;
            acco[nf][2] *= cr1; acco[nf][3] *= cr1;
        }

#pragma unroll
        for (int kf2 = 0; kf2 < 4; kf2++) {
            uint32_t aPh[4], aPl[4];
            split_pack2(accs[2*kf2][0],   accs[2*kf2][1],   aPh[0], aPl[0]);
            split_pack2(accs[2*kf2][2],   accs[2*kf2][3],   aPh[1], aPl[1]);
            split_pack2(accs[2*kf2+1][0], accs[2*kf2+1][1], aPh[2], aPl[2]);
            split_pack2(accs[2*kf2+1][2], accs[2*kf2+1][3], aPh[3], aPl[3]);
#pragma unroll
            for (int nfp2 = 0; nfp2 < 4; nfp2++) {
                const uint32_t row  = (uint32_t)(16*kf2 + ((lane >> 3) & 1) * 8 + (lane & 7));
                const uint32_t colb = (uint32_t)(nfp2 * 32 + (lane >> 4) * 16);
                const uint32_t so   = SWZ(row * 128 + colb);
                uint32_t vhf[4], vlf[4];
                ldsm4t(vhf, stb + 2*ATT_KVB + so);
                ldsm4t(vlf, stb + 3*ATT_KVB + so);
                mma_bf16(acco[2*nfp2],   aPh, &vhf[0]);
                mma_bf16(acco[2*nfp2],   aPh, &vlf[0]);
                mma_bf16(acco[2*nfp2],   aPl, &vhf[0]);
                mma_bf16(acco[2*nfp2+1], aPh, &vhf[2]);
                mma_bf16(acco[2*nfp2+1], aPh, &vlf[2]);
                mma_bf16(acco[2*nfp2+1], aPl, &vhf[2]);
            }
        }

        __syncthreads();
        if (c + 3 < NT) {
            att_load_stage(sb + 2*ATT_QB + stg * ATT_STG,
                           Kh_, Kl_, Vh_, Vl_, tb, (c + 3) * 64, tid);
            cpa_commit();
        }
        stg = (stg + 1 == 3) ? 0 : stg + 1;
    }

    const float inv0 = 1.f / l0v, inv1 = 1.f / l1v;
    const int b = bh >> 4, h = bh & 15;
    const int s0 = q0 + warp * 16 + (lane >> 2), s1 = s0 + 8;
#pragma unroll
    for (int nf = 0; nf < 8; nf++) {
        const int col = h * HDm + nf * 8 + (lane & 3) * 2;
        const size_t o0 = (size_t)(b * Sq + s0) * Dm + col;
        const size_t o1 = (size_t)(b * Sq + s1) * Dm + col;
        split_store2(acco[nf][0] * inv0, acco[nf][1] * inv0, Ohi + o0, Olo + o0);
        split_store2(acco[nf][2] * inv1, acco[nf][3] * inv1, Ohi + o1, Olo + o1);
    }
}

// ---------------------------------------------------------------------------
extern "C" void kernel_launch(void* const* d_in, const int* in_sizes, int n_in,
                              void* d_out, int out_size)
{
    const float* x    = (const float*)d_in[0];
    const float* Wq   = (const float*)d_in[1];
    const float* bq   = (const float*)d_in[2];
    const float* Wk   = (const float*)d_in[3];
    const float* bk   = (const float*)d_in[4];
    const float* Wv   = (const float*)d_in[5];
    const float* bv   = (const float*)d_in[6];
    const float* Wo   = (const float*)d_in[7];
    const float* bo   = (const float*)d_in[8];
    const float* ln1g = (const float*)d_in[9];
    const float* ln1b = (const float*)d_in[10];
    const float* ln2g = (const float*)d_in[11];
    const float* ln2b = (const float*)d_in[12];
    const float* W1   = (const float*)d_in[13];
    const float* b1   = (const float*)d_in[14];
    const float* W2   = (const float*)d_in[15];
    const float* b2   = (const float*)d_in[16];
    float* out = (float*)d_out;

    float *x2;
    __nv_bfloat16 *ahi, *alo, *hhi, *hlo;
    __nv_bfloat16 *qh, *ql, *kh, *kl, *vh, *vl;
    __nv_bfloat16 *wqh, *wql, *wkh, *wkl, *wvh, *wvl, *woh, *wol, *w1h, *w1l, *w2h, *w2l;
    cudaGetSymbolAddress((void**)&x2,  g_x2);
    cudaGetSymbolAddress((void**)&ahi, g_ahi);
    cudaGetSymbolAddress((void**)&alo, g_alo);
    cudaGetSymbolAddress((void**)&hhi, g_hhi);
    cudaGetSymbolAddress((void**)&hlo, g_hlo);
    cudaGetSymbolAddress((void**)&qh,  g_qh); cudaGetSymbolAddress((void**)&ql, g_ql);
    cudaGetSymbolAddress((void**)&kh,  g_kh); cudaGetSymbolAddress((void**)&kl, g_kl);
    cudaGetSymbolAddress((void**)&vh,  g_vh); cudaGetSymbolAddress((void**)&vl, g_vl);
    cudaGetSymbolAddress((void**)&wqh, g_wqh); cudaGetSymbolAddress((void**)&wql, g_wql);
    cudaGetSymbolAddress((void**)&wkh, g_wkh); cudaGetSymbolAddress((void**)&wkl, g_wkl);
    cudaGetSymbolAddress((void**)&wvh, g_wvh); cudaGetSymbolAddress((void**)&wvl, g_wvl);
    cudaGetSymbolAddress((void**)&woh, g_woh); cudaGetSymbolAddress((void**)&wol, g_wol);
    cudaGetSymbolAddress((void**)&w1h, g_w1h); cudaGetSymbolAddress((void**)&w1l, g_w1l);
    cudaGetSymbolAddress((void**)&w2h, g_w2h); cudaGetSymbolAddress((void**)&w2l, g_w2l);

    cudaFuncSetAttribute(attn_hmma, cudaFuncAttributeMaxDynamicSharedMemorySize, ATT_SMEM);
    cudaFuncSetAttribute(gemm_hmma<1>, cudaFuncAttributeMaxDynamicSharedMemorySize, GEMM_SMEM);
    cudaFuncSetAttribute(gemm_hmma<2>, cudaFuncAttributeMaxDynamicSharedMemorySize, GEMM_SMEM);
    cudaFuncSetAttribute(gemm_hmma<3>, cudaFuncAttributeMaxDynamicSharedMemorySize, GEMM_SMEM);

    const dim3 blk(256);
    const dim3 wblk(32, 8);
    const dim3 gP (Dm  / TNq, NTOK / TMq);   // (4, 64)
    const dim3 gF1(DFm / TNq, NTOK / TMq);   // (16, 64)

    // 0) weight convert + transpose (hi/lo bf16, [N,K])
    wconv_kernel<<<dim3(Dm/32,  Dm/32),  wblk>>>(Wq, wqh, wql, Dm,  Dm);
    wconv_kernel<<<dim3(Dm/32,  Dm/32),  wblk>>>(Wk, wkh, wkl, Dm,  Dm);
    wconv_kernel<<<dim3(Dm/32,  Dm/32),  wblk>>>(Wv, wvh, wvl, Dm,  Dm);
    wconv_kernel<<<dim3(Dm/32,  Dm/32),  wblk>>>(Wo, woh, wol, Dm,  Dm);
    wconv_kernel<<<dim3(DFm/32, Dm/32),  wblk>>>(W1, w1h, w1l, Dm,  DFm);
    wconv_kernel<<<dim3(Dm/32,  DFm/32), wblk>>>(W2, w2h, w2l, DFm, Dm);

    // 1) LN1 -> bf16 split
    ln_kernel<<<NTOK, blk>>>(x, ln1g, ln1b, ahi, alo);
    // 2) Q/K/V projections (HMMA) -> bf16 hi/lo scattered [B,H,S,64]
    gemm_hmma<3><<<gP, blk, GEMM_SMEM>>>(ahi, alo, wqh, wql, bq, nullptr, nullptr, qh, ql, Dm, Dm);
    gemm_hmma<3><<<gP, blk, GEMM_SMEM>>>(ahi, alo, wkh, wkl, bk, nullptr, nullptr, kh, kl, Dm, Dm);
    gemm_hmma<3><<<gP, blk, GEMM_SMEM>>>(ahi, alo, wvh, wvl, bv, nullptr, nullptr, vh, vl, Dm, Dm);
    // 3) attention (HMMA) -> bf16 hi/lo [B,S,D]
    attn_hmma<<<dim3(Sq / 128, Bq * Hh), blk, ATT_SMEM>>>(qh, ql, kh, kl, vh, vl, ahi, alo);
    // 4) output projection + residual -> x2 (f32)
    gemm_hmma<2><<<gP, blk, GEMM_SMEM>>>(ahi, alo, woh, wol, bo, x, x2, nullptr, nullptr, Dm, Dm);
    // 5) LN2 -> bf16 split
    ln_kernel<<<NTOK, blk>>>(x2, ln2g, ln2b, ahi, alo);
    // 6) FFN up + exact GELU -> bf16 split h
    gemm_hmma<1><<<gF1, blk, GEMM_SMEM>>>(ahi, alo, w1h, w1l, b1, nullptr, nullptr, hhi, hlo, DFm, Dm);
    // 7) FFN down + residual -> out (f32)
    gemm_hmma<2><<<gP, blk, GEMM_SMEM>>>(hhi, hlo, w2h, w2l, b2, x2, out, nullptr, nullptr, Dm, DFm);
}

// round 9
// speedup vs baseline: 1.2638x; 1.2638x over previous
#include <cuda_runtime.h>
#include <cuda_fp16.h>
#include <math.h>
#include <stdint.h>

// Problem constants
#define Bq   4
#define Sq   2048
#define Dm   1024
#define Hh   16
#define HDm  64
#define DFm  4096
#define NTOK (Bq*Sq)   // 8192
#define QKV_SZ (NTOK*Dm)

// ---------------------------------------------------------------------------
// Scratch (module-load allocated)
// ---------------------------------------------------------------------------
__device__ float g_x2 [NTOK*Dm];
__device__ float g_bqkv[3*Dm];

__device__ __half g_ahi[NTOK*Dm];
__device__ __half g_alo[NTOK*Dm];
__device__ __half g_hhi[NTOK*DFm];
__device__ __half g_hlo[NTOK*DFm];

__device__ __half g_qh[QKV_SZ], g_ql[QKV_SZ];
__device__ __half g_kh[QKV_SZ], g_kl[QKV_SZ];
__device__ __half g_vh[QKV_SZ], g_vl[QKV_SZ];

__device__ __half g_wqkv[3*Dm*Dm];     // fused QKV weights, [3072, 1024] K-major
__device__ __half g_wo [Dm*Dm];
__device__ __half g_w1 [Dm*DFm];
__device__ __half g_w2 [Dm*DFm];

// ---------------------------------------------------------------------------
// PTX helpers (base-target safe: cp.async + ldmatrix + mma.sync only)
// ---------------------------------------------------------------------------
__device__ __forceinline__ uint32_t s2u(const void* p) {
    uint32_t a;
    asm("{ .reg .u64 t; cvta.to.shared.u64 t, %1; cvt.u32.u64 %0, t; }"
        : "=r"(a) : "l"(p));
    return a;
}
__device__ __forceinline__ void cpa16(uint32_t d, const void* s) {
    asm volatile("cp.async.cg.shared.global [%0], [%1], 16;"
                 :: "r"(d), "l"(s) : "memory");
}
__device__ __forceinline__ void cpa_commit() {
    asm volatile("cp.async.commit_group;" ::: "memory");
}
template<int NN> __device__ __forceinline__ void cpa_wait() {
    asm volatile("cp.async.wait_group %0;" :: "n"(NN) : "memory");
}
__device__ __forceinline__ void ldsm4(uint32_t* r, uint32_t a) {
    asm volatile("ldmatrix.sync.aligned.m8n8.x4.shared.b16 {%0,%1,%2,%3}, [%4];"
                 : "=r"(r[0]), "=r"(r[1]), "=r"(r[2]), "=r"(r[3]) : "r"(a));
}
__device__ __forceinline__ void ldsm4t(uint32_t* r, uint32_t a) {
    asm volatile("ldmatrix.sync.aligned.m8n8.x4.trans.shared.b16 {%0,%1,%2,%3}, [%4];"
                 : "=r"(r[0]), "=r"(r[1]), "=r"(r[2]), "=r"(r[3]) : "r"(a));
}
__device__ __forceinline__ void ldsm2(uint32_t* r, uint32_t a) {
    asm volatile("ldmatrix.sync.aligned.m8n8.x2.shared.b16 {%0,%1}, [%2];"
                 : "=r"(r[0]), "=r"(r[1]) : "r"(a));
}
__device__ __forceinline__ void mma_f16(float* d, const uint32_t* a, const uint32_t* b) {
    asm volatile(
        "mma.sync.aligned.m16n8k16.row.col.f32.f16.f16.f32 "
        "{%0,%1,%2,%3}, {%4,%5,%6,%7}, {%8,%9}, {%0,%1,%2,%3};"
        : "+f"(d[0]), "+f"(d[1]), "+f"(d[2]), "+f"(d[3])
        : "r"(a[0]), "r"(a[1]), "r"(a[2]), "r"(a[3]), "r"(b[0]), "r"(b[1]));
}

// split fp32 pairs into fp16 hi/lo
__device__ __forceinline__ void split_pack2(float x, float y, uint32_t& H, uint32_t& L) {
    __half hx = __float2half(x), hy = __float2half(y);
    float lx = x - __half2float(hx), ly = y - __half2float(hy);
    __half gx = __float2half(lx), gy = __float2half(ly);
    H = (uint32_t)__half_as_ushort(hx) | ((uint32_t)__half_as_ushort(hy) << 16);
    L = (uint32_t)__half_as_ushort(gx) | ((uint32_t)__half_as_ushort(gy) << 16);
}
__device__ __forceinline__ void split_store2(float x, float y,
                                             __half* hi, __half* lo) {
    uint32_t H, L;
    split_pack2(x, y, H, L);
    *(uint32_t*)hi = H;
    *(uint32_t*)lo = L;
}
__device__ __forceinline__ void split_store4(float4 v, __half* hi, __half* lo) {
    split_store2(v.x, v.y, hi,     lo);
    split_store2(v.z, v.w, hi + 2, lo + 2);
}

#define SWZ(x) ((x) ^ (((x) >> 3) & 0x70))

// ---------------------------------------------------------------------------
// LayerNorm: one block per row, emits fp16 hi/lo split directly
// ---------------------------------------------------------------------------
__global__ __launch_bounds__(256)
void ln_kernel(const float* __restrict__ X, const float* __restrict__ G,
               const float* __restrict__ Bt,
               __half* __restrict__ Yhi, __half* __restrict__ Ylo)
{
    __shared__ float ss[8], sq[8];
    const int r = blockIdx.x, tid = threadIdx.x;
    const float* xr = X + (size_t)r * Dm;
    float4 v = *(const float4*)(xr + tid * 4);
    float s = v.x + v.y + v.z + v.w;
    float q = v.x*v.x + v.y*v.y + v.z*v.z + v.w*v.w;
#pragma unroll
    for (int off = 16; off >= 1; off >>= 1) {
        s += __shfl_xor_sync(0xffffffffu, s, off);
        q += __shfl_xor_sync(0xffffffffu, q, off);
    }
    if ((tid & 31) == 0) { ss[tid >> 5] = s; sq[tid >> 5] = q; }
    __syncthreads();
    float ts = 0.f, tq = 0.f;
#pragma unroll
    for (int w = 0; w < 8; w++) { ts += ss[w]; tq += sq[w]; }
    const float mu   = ts * (1.0f / Dm);
    const float var  = tq * (1.0f / Dm) - mu * mu;
    const float rstd = rsqrtf(var + 1e-5f);
    float4 g4 = *(const float4*)(G  + tid * 4);
    float4 b4 = *(const float4*)(Bt + tid * 4);
    float4 o;
    o.x = (v.x - mu) * rstd * g4.x + b4.x;
    o.y = (v.y - mu) * rstd * g4.y + b4.y;
    o.z = (v.z - mu) * rstd * g4.z + b4.z;
    o.w = (v.w - mu) * rstd * g4.w + b4.w;
    const size_t idx = (size_t)r * Dm + tid * 4;
    split_store4(o, Yhi + idx, Ylo + idx);
}

// ---------------------------------------------------------------------------
// Weight convert+transpose: W[K,N] f32 -> WT [N,K] fp16 (single, rounded)
// ---------------------------------------------------------------------------
__global__ __launch_bounds__(256)
void wconv_kernel(const float* __restrict__ W, __half* __restrict__ Th,
                  int K, int N)
{
    __shared__ float t[32][33];
    const int n0 = blockIdx.x * 32, k0 = blockIdx.y * 32;
    const int tx = threadIdx.x, ty = threadIdx.y;
#pragma unroll
    for (int i = 0; i < 4; i++)
        t[ty + i*8][tx] = W[(size_t)(k0 + ty + i*8) * N + n0 + tx];
    __syncthreads();
#pragma unroll
    for (int i = 0; i < 4; i++) {
        const int r = ty + i*8;
        Th[(size_t)(n0 + r) * K + k0 + tx] = __float2half(t[tx][r]);
    }
}

// ---------------------------------------------------------------------------
// HMMA fp16 2-product GEMM: C[M,N] = (Ahi+Alo)[M,K] @ Wh[K,N] + bias
//   A split hi/lo fp16 row-major; W single fp16 [N,K] K-major.
// CTA tile 128x128, K-chunk 64, 4-stage cp.async pipeline (48KB/stage).
// 8 warps as 2(M)x4(N); warp tile 64x32.
// MODE: 1 = bias+GELU -> fp16 hi/lo, 2 = bias+residual -> f32,
//       3 = bias -> fp16 hi/lo scatter to [B,H,S,64], target by n0>>10
// ---------------------------------------------------------------------------
#define TMq 128
#define TNq 128
#define TILE_B   16384               // one tensor tile (128 x 128B)
#define STG_BYTES (3*TILE_B)         // Ah, Al, Bh = 49152
#define GEMM_SMEM (4*STG_BYTES)      // 196608
#define OFF_AL (TILE_B)
#define OFF_BH (2*TILE_B)

__device__ __forceinline__ void load_stage(
    uint32_t st,
    const __half* __restrict__ Ahi, const __half* __restrict__ Alo,
    const __half* __restrict__ Bh,
    int m0, int n0, int kc, int K, int tid)
{
#pragma unroll
    for (int j = 0; j < 4; j++) {          // 128 rows x 8 chunks of 16B
        const int i = tid + j * 256;
        const int r = i >> 3, c = i & 7;
        const uint32_t off = SWZ((uint32_t)(r * 128 + c * 16));
        const size_t ga = (size_t)(m0 + r) * K + kc + c * 8;
        const size_t gb = (size_t)(n0 + r) * K + kc + c * 8;
        cpa16(st + off,          Ahi + ga);
        cpa16(st + OFF_AL + off, Alo + ga);
        cpa16(st + OFF_BH + off, Bh  + gb);
    }
}

template<int MODE>
__global__ __launch_bounds__(256, 1)
void gemm_hmma(const __half* __restrict__ Ahi, const __half* __restrict__ Alo,
               const __half* __restrict__ Bh,
               const float* __restrict__ bias, const float* __restrict__ res,
               float* __restrict__ Cf,
               __half* __restrict__ Cqh, __half* __restrict__ Cql,
               __half* __restrict__ Ckh, __half* __restrict__ Ckl,
               __half* __restrict__ Cvh, __half* __restrict__ Cvl,
               int N, int K)
{
    extern __shared__ __align__(1024) char smem[];
    const uint32_t sb = s2u(smem);
    const int tid = threadIdx.x, lane = tid & 31, warp = tid >> 5;
    const int wm = warp >> 2, wn = warp & 3;
    const int m0 = blockIdx.y * TMq, n0 = blockIdx.x * TNq;

    float acc[4][4][4];
#pragma unroll
    for (int a = 0; a < 4; a++)
#pragma unroll
        for (int b = 0; b < 4; b++)
#pragma unroll
            for (int c = 0; c < 4; c++) acc[a][b][c] = 0.f;

    uint32_t rowA[4], rowB[4];
#pragma unroll
    for (int mf = 0; mf < 4; mf++)
        rowA[mf] = (uint32_t)((wm*64 + mf*16 + (lane & 15)) * 128 + (lane >> 4) * 16);
#pragma unroll
    for (int nf = 0; nf < 4; nf++)
        rowB[nf] = (uint32_t)((wn*32 + nf*8 + (lane & 7)) * 128 + ((lane >> 3) & 1) * 16);

    const int NC = K >> 6;
    load_stage(sb,               Ahi, Alo, Bh, m0, n0, 0,   K, tid); cpa_commit();
    load_stage(sb +   STG_BYTES, Ahi, Alo, Bh, m0, n0, 64,  K, tid); cpa_commit();
    load_stage(sb + 2*STG_BYTES, Ahi, Alo, Bh, m0, n0, 128, K, tid); cpa_commit();
    load_stage(sb + 3*STG_BYTES, Ahi, Alo, Bh, m0, n0, 192, K, tid); cpa_commit();

    int stg = 0;
    for (int c = 0; c < NC; c++) {
        const int rem = NC - 1 - c;
        if (rem >= 3)      cpa_wait<3>();
        else if (rem == 2) cpa_wait<2>();
        else if (rem == 1) cpa_wait<1>();
        else               cpa_wait<0>();
        __syncthreads();

        const uint32_t stA = sb + stg * STG_BYTES;
#pragma unroll
        for (int ks = 0; ks < 4; ks++) {
            const uint32_t ko = ks * 32;
            uint32_t ah[4][4], al[4][4], bh[4][2];
#pragma unroll
            for (int mf = 0; mf < 4; mf++) {
                const uint32_t so = SWZ(rowA[mf] + ko);
                ldsm4(ah[mf], stA + so);
                ldsm4(al[mf], stA + OFF_AL + so);
            }
#pragma unroll
            for (int nf = 0; nf < 4; nf++) {
                const uint32_t so = SWZ(rowB[nf] + ko);
                ldsm2(bh[nf], stA + OFF_BH + so);
            }
#pragma unroll
            for (int mf = 0; mf < 4; mf++)
#pragma unroll
                for (int nf = 0; nf < 4; nf++) {
                    mma_f16(acc[mf][nf], ah[mf], bh[nf]);
                    mma_f16(acc[mf][nf], al[mf], bh[nf]);
                }
        }
        __syncthreads();
        if (c + 4 < NC) {
            load_stage(stA, Ahi, Alo, Bh, m0, n0, (c + 4) * 64, K, tid);
            cpa_commit();
        }
        stg = (stg + 1) & 3;
    }

    const int qr = lane >> 2, qc = (lane & 3) * 2;
    // MODE 3: select projection target by CTA column block (uniform)
    __half* Oh = nullptr; __half* Ol = nullptr;
    if (MODE == 3) {
        const int which = n0 >> 10;
        Oh = (which == 0) ? Cqh : (which == 1) ? Ckh : Cvh;
        Ol = (which == 0) ? Cql : (which == 1) ? Ckl : Cvl;
    }
#pragma unroll
    for (int mf = 0; mf < 4; mf++) {
#pragma unroll
        for (int nf = 0; nf < 4; nf++) {
            const int row = m0 + wm*64 + mf*16 + qr;
            const int col = n0 + wn*32 + nf*8 + qc;
            float2 bv = *(const float2*)(bias + col);
            float x0 = acc[mf][nf][0] + bv.x, x1 = acc[mf][nf][1] + bv.y;
            float y0 = acc[mf][nf][2] + bv.x, y1 = acc[mf][nf][3] + bv.y;
            if (MODE == 1) {
                x0 *= normcdff(x0); x1 *= normcdff(x1);
                y0 *= normcdff(y0); y1 *= normcdff(y1);
                const size_t o0 = (size_t)row * N + col;
                const size_t o1 = (size_t)(row + 8) * N + col;
                split_store2(x0, x1, Cqh + o0, Cql + o0);
                split_store2(y0, y1, Cqh + o1, Cql + o1);
            } else if (MODE == 2) {
                const size_t o0 = (size_t)row * N + col;
                const size_t o1 = (size_t)(row + 8) * N + col;
                float2 r0 = *(const float2*)(res + o0);
                float2 r1 = *(const float2*)(res + o1);
                *(float2*)(Cf + o0) = make_float2(x0 + r0.x, x1 + r0.y);
                *(float2*)(Cf + o1) = make_float2(y0 + r1.x, y1 + r1.y);
            } else {
                const int coll = col & 1023;
                const int h = coll >> 6, hd = coll & 63;
                const int b0r = row >> 11, s0 = row & 2047;
                const int b1r = (row + 8) >> 11, s1 = (row + 8) & 2047;
                const size_t o0 = ((size_t)(b0r * Hh + h) * Sq + s0) * HDm + hd;
                const size_t o1 = ((size_t)(b1r * Hh + h) * Sq + s1) * HDm + hd;
                split_store2(x0, x1, Oh + o0, Ol + o0);
                split_store2(y0, y1, Oh + o1, Ol + o1);
            }
        }
    }
}

// ---------------------------------------------------------------------------
// HMMA flash attention with split-fp16 QK^T and PV (structure proven in R7).
// ---------------------------------------------------------------------------
#define ATT_QB   16384                    // one Q tensor tile (128 x 128B)
#define ATT_KVB  8192                     // one KV tensor tile (64 x 128B)
#define ATT_STG  (4*ATT_KVB)              // kh, kl, vh, vl
#define ATT_SMEM (2*ATT_QB + 3*ATT_STG)   // 131072

__device__ __forceinline__ void att_load_stage(
    uint32_t st, const __half* __restrict__ Kh, const __half* __restrict__ Kl,
    const __half* __restrict__ Vh, const __half* __restrict__ Vl,
    size_t tb, int kv0, int tid)
{
#pragma unroll
    for (int j = 0; j < 8; j++) {
        const int i = tid + j * 256;
        const int t = i >> 9;
        const int r = (i >> 3) & 63;
        const int c = i & 7;
        const __half* src = (t == 0) ? Kh : (t == 1) ? Kl : (t == 2) ? Vh : Vl;
        cpa16(st + t * ATT_KVB + SWZ((uint32_t)(r * 128 + c * 16)),
              src + tb + (size_t)(kv0 + r) * HDm + c * 8);
    }
}

__global__ __launch_bounds__(256, 1)
void attn_hmma(const __half* __restrict__ Qh_, const __half* __restrict__ Ql_,
               const __half* __restrict__ Kh_, const __half* __restrict__ Kl_,
               const __half* __restrict__ Vh_, const __half* __restrict__ Vl_,
               __half* __restrict__ Ohi, __half* __restrict__ Olo)
{
    extern __shared__ __align__(1024) char smem[];
    const uint32_t sb = s2u(smem);
    const int tid = threadIdx.x, lane = tid & 31, warp = tid >> 5;
    const int bh = blockIdx.y;
    const int q0 = blockIdx.x * 128;
    const size_t tb = (size_t)bh * Sq * HDm;

    att_load_stage(sb + 2*ATT_QB,             Kh_, Kl_, Vh_, Vl_, tb, 0,   tid); cpa_commit();
    att_load_stage(sb + 2*ATT_QB +   ATT_STG, Kh_, Kl_, Vh_, Vl_, tb, 64,  tid); cpa_commit();
    att_load_stage(sb + 2*ATT_QB + 2*ATT_STG, Kh_, Kl_, Vh_, Vl_, tb, 128, tid); cpa_commit();
#pragma unroll
    for (int j = 0; j < 8; j++) {
        const int i = tid + j * 256;
        const int t = i >> 10;
        const int r = (i >> 3) & 127;
        const int c = i & 7;
        const __half* src = t ? Ql_ : Qh_;
        cpa16(sb + t * ATT_QB + SWZ((uint32_t)(r * 128 + c * 16)),
              src + tb + (size_t)(q0 + r) * HDm + c * 8);
    }
    cpa_commit();
    cpa_wait<0>();
    __syncthreads();

    uint32_t qfh[4][4], qfl[4][4];
    {
        const uint32_t qrow = (uint32_t)((16*warp + (lane & 15)) * 128 + (lane >> 4) * 16);
#pragma unroll
        for (int kf = 0; kf < 4; kf++) {
            const uint32_t so = SWZ(qrow + kf * 32);
            ldsm4(qfh[kf], sb + so);
            ldsm4(qfl[kf], sb + ATT_QB + so);
        }
    }

    float acco[8][4];
#pragma unroll
    for (int nf = 0; nf < 8; nf++)
#pragma unroll
        for (int c = 0; c < 4; c++) acco[nf][c] = 0.f;
    float m0v = -1e30f, m1v = -1e30f, l0v = 0.f, l1v = 0.f;

    const int NT = Sq / 64;   // 32
    int stg = 0;
    for (int c = 0; c < NT; c++) {
        const int rem = NT - 1 - c;
        if (rem >= 2)      cpa_wait<2>();
        else if (rem == 1) cpa_wait<1>();
        else               cpa_wait<0>();
        __syncthreads();

        const uint32_t stb = sb + 2*ATT_QB + stg * ATT_STG;

        float accs[8][4];
#pragma unroll
        for (int nf = 0; nf < 8; nf++)
#pragma unroll
            for (int q4 = 0; q4 < 4; q4++) accs[nf][q4] = 0.f;

#pragma unroll
        for (int kf = 0; kf < 4; kf++) {
            uint32_t bhf[4][4], blf[4][4];
#pragma unroll
            for (int nfp = 0; nfp < 4; nfp++) {
                const uint32_t row = (uint32_t)(16*nfp + ((lane >> 4) << 3) + (lane & 7));
                const uint32_t kb  = (uint32_t)(kf * 32 + ((lane >> 3) & 1) * 16);
                const uint32_t so  = SWZ(row * 128 + kb);
                ldsm4(bhf[nfp], stb + so);
                ldsm4(blf[nfp], stb + ATT_KVB + so);
            }
#pragma unroll
            for (int nfp = 0; nfp < 4; nfp++) {
                mma_f16(accs[2*nfp],   qfh[kf], &bhf[nfp][0]);
                mma_f16(accs[2*nfp],   qfh[kf], &blf[nfp][0]);
                mma_f16(accs[2*nfp],   qfl[kf], &bhf[nfp][0]);
                mma_f16(accs[2*nfp+1], qfh[kf], &bhf[nfp][2]);
                mma_f16(accs[2*nfp+1], qfh[kf], &blf[nfp][2]);
                mma_f16(accs[2*nfp+1], qfl[kf], &bhf[nfp][2]);
            }
        }

        float mx0 = -1e30f, mx1 = -1e30f;
#pragma unroll
        for (int nf = 0; nf < 8; nf++) {
            mx0 = fmaxf(mx0, fmaxf(accs[nf][0], accs[nf][1]));
            mx1 = fmaxf(mx1, fmaxf(accs[nf][2], accs[nf][3]));
        }
        mx0 *= 0.125f; mx1 *= 0.125f;
#pragma unroll
        for (int off = 1; off <= 2; off <<= 1) {
            mx0 = fmaxf(mx0, __shfl_xor_sync(0xffffffffu, mx0, off));
            mx1 = fmaxf(mx1, __shfl_xor_sync(0xffffffffu, mx1, off));
        }
        const float mn0 = fmaxf(m0v, mx0), mn1 = fmaxf(m1v, mx1);
        const float cr0 = __expf(m0v - mn0), cr1 = __expf(m1v - mn1);
        float sum0 = 0.f, sum1 = 0.f;
#pragma unroll
        for (int nf = 0; nf < 8; nf++) {
            float p0 = __expf(fmaf(accs[nf][0], 0.125f, -mn0));
            float p1 = __expf(fmaf(accs[nf][1], 0.125f, -mn0));
            float p2 = __expf(fmaf(accs[nf][2], 0.125f, -mn1));
            float p3 = __expf(fmaf(accs[nf][3], 0.125f, -mn1));
            accs[nf][0] = p0; accs[nf][1] = p1; accs[nf][2] = p2; accs[nf][3] = p3;
            sum0 += p0 + p1; sum1 += p2 + p3;
        }
#pragma unroll
        for (int off = 1; off <= 2; off <<= 1) {
            sum0 += __shfl_xor_sync(0xffffffffu, sum0, off);
            sum1 += __shfl_xor_sync(0xffffffffu, sum1, off);
        }
        l0v = l0v * cr0 + sum0;  m0v = mn0;
        l1v = l1v * cr1 + sum1;  m1v = mn1;
#pragma unroll
        for (int nf = 0; nf < 8; nf++) {
            acco[nf][0] *= cr0; acco[nf][1] *= cr0;
            acco[nf][2] *= cr1; acco[nf][3] *= cr1;
        }

#pragma unroll
        for (int kf2 = 0; kf2 < 4; kf2++) {
            uint32_t aPh[4], aPl[4];
            split_pack2(accs[2*kf2][0],   accs[2*kf2][1],   aPh[0], aPl[0]);
            split_pack2(accs[2*kf2][2],   accs[2*kf2][3],   aPh[1], aPl[1]);
            split_pack2(accs[2*kf2+1][0], accs[2*kf2+1][1], aPh[2], aPl[2]);
            split_pack2(accs[2*kf2+1][2], accs[2*kf2+1][3], aPh[3], aPl[3]);
#pragma unroll
            for (int nfp2 = 0; nfp2 < 4; nfp2++) {
                const uint32_t row  = (uint32_t)(16*kf2 + ((lane >> 3) & 1) * 8 + (lane & 7));
                const uint32_t colb = (uint32_t)(nfp2 * 32 + (lane >> 4) * 16);
                const uint32_t so   = SWZ(row * 128 + colb);
                uint32_t vhf[4], vlf[4];
                ldsm4t(vhf, stb + 2*ATT_KVB + so);
                ldsm4t(vlf, stb + 3*ATT_KVB + so);
                mma_f16(acco[2*nfp2],   aPh, &vhf[0]);
                mma_f16(acco[2*nfp2],   aPh, &vlf[0]);
                mma_f16(acco[2*nfp2],   aPl, &vhf[0]);
                mma_f16(acco[2*nfp2+1], aPh, &vhf[2]);
                mma_f16(acco[2*nfp2+1], aPh, &vlf[2]);
                mma_f16(acco[2*nfp2+1], aPl, &vhf[2]);
            }
        }

        __syncthreads();
        if (c + 3 < NT) {
            att_load_stage(sb + 2*ATT_QB + stg * ATT_STG,
                           Kh_, Kl_, Vh_, Vl_, tb, (c + 3) * 64, tid);
            cpa_commit();
        }
        stg = (stg + 1 == 3) ? 0 : stg + 1;
    }

    const float inv0 = 1.f / l0v, inv1 = 1.f / l1v;
    const int b = bh >> 4, h = bh & 15;
    const int s0 = q0 + warp * 16 + (lane >> 2), s1 = s0 + 8;
#pragma unroll
    for (int nf = 0; nf < 8; nf++) {
        const int col = h * HDm + nf * 8 + (lane & 3) * 2;
        const size_t o0 = (size_t)(b * Sq + s0) * Dm + col;
        const size_t o1 = (size_t)(b * Sq + s1) * Dm + col;
        split_store2(acco[nf][0] * inv0, acco[nf][1] * inv0, Ohi + o0, Olo + o0);
        split_store2(acco[nf][2] * inv1, acco[nf][3] * inv1, Ohi + o1, Olo + o1);
    }
}

// ---------------------------------------------------------------------------
extern "C" void kernel_launch(void* const* d_in, const int* in_sizes, int n_in,
                              void* d_out, int out_size)
{
    const float* x    = (const float*)d_in[0];
    const float* Wq   = (const float*)d_in[1];
    const float* bq   = (const float*)d_in[2];
    const float* Wk   = (const float*)d_in[3];
    const float* bk   = (const float*)d_in[4];
    const float* Wv   = (const float*)d_in[5];
    const float* bv   = (const float*)d_in[6];
    const float* Wo   = (const float*)d_in[7];
    const float* bo   = (const float*)d_in[8];
    const float* ln1g = (const float*)d_in[9];
    const float* ln1b = (const float*)d_in[10];
    const float* ln2g = (const float*)d_in[11];
    const float* ln2b = (const float*)d_in[12];
    const float* W1   = (const float*)d_in[13];
    const float* b1   = (const float*)d_in[14];
    const float* W2   = (const float*)d_in[15];
    const float* b2   = (const float*)d_in[16];
    float* out = (float*)d_out;

    float *x2, *bqkv;
    __half *ahi, *alo, *hhi, *hlo;
    __half *qh, *ql, *kh, *kl, *vh, *vl;
    __half *wqkv, *wo, *w1, *w2;
    cudaGetSymbolAddress((void**)&x2,   g_x2);
    cudaGetSymbolAddress((void**)&bqkv, g_bqkv);
    cudaGetSymbolAddress((void**)&ahi,  g_ahi);
    cudaGetSymbolAddress((void**)&alo,  g_alo);
    cudaGetSymbolAddress((void**)&hhi,  g_hhi);
    cudaGetSymbolAddress((void**)&hlo,  g_hlo);
    cudaGetSymbolAddress((void**)&qh,   g_qh); cudaGetSymbolAddress((void**)&ql, g_ql);
    cudaGetSymbolAddress((void**)&kh,   g_kh); cudaGetSymbolAddress((void**)&kl, g_kl);
    cudaGetSymbolAddress((void**)&vh,   g_vh); cudaGetSymbolAddress((void**)&vl, g_vl);
    cudaGetSymbolAddress((void**)&wqkv, g_wqkv);
    cudaGetSymbolAddress((void**)&wo,   g_wo);
    cudaGetSymbolAddress((void**)&w1,   g_w1);
    cudaGetSymbolAddress((void**)&w2,   g_w2);

    cudaFuncSetAttribute(attn_hmma, cudaFuncAttributeMaxDynamicSharedMemorySize, ATT_SMEM);
    cudaFuncSetAttribute(gemm_hmma<1>, cudaFuncAttributeMaxDynamicSharedMemorySize, GEMM_SMEM);
    cudaFuncSetAttribute(gemm_hmma<2>, cudaFuncAttributeMaxDynamicSharedMemorySize, GEMM_SMEM);
    cudaFuncSetAttribute(gemm_hmma<3>, cudaFuncAttributeMaxDynamicSharedMemorySize, GEMM_SMEM);

    const dim3 blk(256);
    const dim3 wblk(32, 8);
    const dim3 gQKV(3*Dm / TNq, NTOK / TMq);  // (24, 64)
    const dim3 gP  (Dm   / TNq, NTOK / TMq);  // (8, 64)
    const dim3 gF1 (DFm  / TNq, NTOK / TMq);  // (32, 64)

    // 0) weight convert + transpose (fp16, [N,K]); QKV concatenated
    wconv_kernel<<<dim3(Dm/32,  Dm/32),  wblk>>>(Wq, wqkv,            Dm,  Dm);
    wconv_kernel<<<dim3(Dm/32,  Dm/32),  wblk>>>(Wk, wqkv + Dm*Dm,    Dm,  Dm);
    wconv_kernel<<<dim3(Dm/32,  Dm/32),  wblk>>>(Wv, wqkv + 2*Dm*Dm,  Dm,  Dm);
    wconv_kernel<<<dim3(Dm/32,  Dm/32),  wblk>>>(Wo, wo,              Dm,  Dm);
    wconv_kernel<<<dim3(DFm/32, Dm/32),  wblk>>>(W1, w1,              Dm,  DFm);
    wconv_kernel<<<dim3(Dm/32,  DFm/32), wblk>>>(W2, w2,              DFm, Dm);
    // fused QKV bias (device-to-device async copies are graph-capturable)
    cudaMemcpyAsync(bqkv,          bq, Dm*sizeof(float), cudaMemcpyDeviceToDevice);
    cudaMemcpyAsync(bqkv +   Dm,   bk, Dm*sizeof(float), cudaMemcpyDeviceToDevice);
    cudaMemcpyAsync(bqkv + 2*Dm,   bv, Dm*sizeof(float), cudaMemcpyDeviceToDevice);

    // 1) LN1 -> fp16 split
    ln_kernel<<<NTOK, blk>>>(x, ln1g, ln1b, ahi, alo);
    // 2) fused QKV projection -> fp16 hi/lo scattered [B,H,S,64]
    gemm_hmma<3><<<gQKV, blk, GEMM_SMEM>>>(ahi, alo, wqkv, bqkv, nullptr, nullptr,
                                           qh, ql, kh, kl, vh, vl, 3*Dm, Dm);
    // 3) attention (HMMA) -> fp16 hi/lo [B,S,D]
    attn_hmma<<<dim3(Sq / 128, Bq * Hh), blk, ATT_SMEM>>>(qh, ql, kh, kl, vh, vl, ahi, alo);
    // 4) output projection + residual -> x2 (f32)
    gemm_hmma<2><<<gP, blk, GEMM_SMEM>>>(ahi, alo, wo, bo, x, x2,
                                         nullptr, nullptr, nullptr, nullptr, nullptr, nullptr,
                                         Dm, Dm);
    // 5) LN2 -> fp16 split
    ln_kernel<<<NTOK, blk>>>(x2, ln2g, ln2b, ahi, alo);
    // 6) FFN up + exact GELU -> fp16 split h
    gemm_hmma<1><<<gF1, blk, GEMM_SMEM>>>(ahi, alo, w1, b1, nullptr, nullptr,
                                          hhi, hlo, nullptr, nullptr, nullptr, nullptr,
                                          DFm, Dm);
    // 7) FFN down + residual -> out (f32)
    gemm_hmma<2><<<gP, blk, GEMM_SMEM>>>(hhi, hlo, w2, b2, x2, out,
                                         nullptr, nullptr, nullptr, nullptr, nullptr, nullptr,
                                         Dm, DFm);
}

// round 10
// speedup vs baseline: 2.2471x; 1.7781x over previous
#include <cuda_runtime.h>
#include <cuda_fp16.h>
#include <math.h>
#include <stdint.h>

// Problem constants
#define Bq   4
#define Sq   2048
#define Dm   1024
#define Hh   16
#define HDm  64
#define DFm  4096
#define NTOK (Bq*Sq)   // 8192
#define QKV_SZ (NTOK*Dm)

// ---------------------------------------------------------------------------
// Scratch (module-load allocated)
// ---------------------------------------------------------------------------
__device__ float g_x2 [NTOK*Dm];
__device__ float g_bqkv[3*Dm];

__device__ __half g_a  [NTOK*Dm];      // LN output / attention output (fp16)
__device__ __half g_h  [NTOK*DFm];     // FFN hidden (fp16)

__device__ __half g_q [QKV_SZ];
__device__ __half g_k [QKV_SZ];
__device__ __half g_v [QKV_SZ];

__device__ __half g_wqkv[3*Dm*Dm];     // fused QKV weights, [3072, 1024] K-major
__device__ __half g_wo [Dm*Dm];
__device__ __half g_w1 [Dm*DFm];
__device__ __half g_w2 [Dm*DFm];

// ---------------------------------------------------------------------------
// PTX helpers (base-target safe: cp.async + ldmatrix + mma.sync only)
// ---------------------------------------------------------------------------
__device__ __forceinline__ uint32_t s2u(const void* p) {
    uint32_t a;
    asm("{ .reg .u64 t; cvta.to.shared.u64 t, %1; cvt.u32.u64 %0, t; }"
        : "=r"(a) : "l"(p));
    return a;
}
__device__ __forceinline__ void cpa16(uint32_t d, const void* s) {
    asm volatile("cp.async.cg.shared.global [%0], [%1], 16;"
                 :: "r"(d), "l"(s) : "memory");
}
__device__ __forceinline__ void cpa_commit() {
    asm volatile("cp.async.commit_group;" ::: "memory");
}
template<int NN> __device__ __forceinline__ void cpa_wait() {
    asm volatile("cp.async.wait_group %0;" :: "n"(NN) : "memory");
}
__device__ __forceinline__ void ldsm4(uint32_t* r, uint32_t a) {
    asm volatile("ldmatrix.sync.aligned.m8n8.x4.shared.b16 {%0,%1,%2,%3}, [%4];"
                 : "=r"(r[0]), "=r"(r[1]), "=r"(r[2]), "=r"(r[3]) : "r"(a));
}
__device__ __forceinline__ void ldsm4t(uint32_t* r, uint32_t a) {
    asm volatile("ldmatrix.sync.aligned.m8n8.x4.trans.shared.b16 {%0,%1,%2,%3}, [%4];"
                 : "=r"(r[0]), "=r"(r[1]), "=r"(r[2]), "=r"(r[3]) : "r"(a));
}
__device__ __forceinline__ void ldsm2(uint32_t* r, uint32_t a) {
    asm volatile("ldmatrix.sync.aligned.m8n8.x2.shared.b16 {%0,%1}, [%2];"
                 : "=r"(r[0]), "=r"(r[1]) : "r"(a));
}
__device__ __forceinline__ void mma_f16(float* d, const uint32_t* a, const uint32_t* b) {
    asm volatile(
        "mma.sync.aligned.m16n8k16.row.col.f32.f16.f16.f32 "
        "{%0,%1,%2,%3}, {%4,%5,%6,%7}, {%8,%9}, {%0,%1,%2,%3};"
        : "+f"(d[0]), "+f"(d[1]), "+f"(d[2]), "+f"(d[3])
        : "r"(a[0]), "r"(a[1]), "r"(a[2]), "r"(a[3]), "r"(b[0]), "r"(b[1]));
}

__device__ __forceinline__ uint32_t pack_h2(float x, float y) {
    __half2 h = __floats2half2_rn(x, y);
    return *(uint32_t*)&h;
}
// split fp32 pair into fp16 hi/lo (used only for attention P)
__device__ __forceinline__ void split_pack2(float x, float y, uint32_t& H, uint32_t& L) {
    __half hx = __float2half(x), hy = __float2half(y);
    float lx = x - __half2float(hx), ly = y - __half2float(hy);
    H = (uint32_t)__half_as_ushort(hx) | ((uint32_t)__half_as_ushort(hy) << 16);
    L = (uint32_t)__half_as_ushort(__float2half(lx)) |
        ((uint32_t)__half_as_ushort(__float2half(ly)) << 16);
}

#define SWZ(x) ((x) ^ (((x) >> 3) & 0x70))

// ---------------------------------------------------------------------------
// LayerNorm: one block per row, emits fp16
// ---------------------------------------------------------------------------
__global__ __launch_bounds__(256)
void ln_kernel(const float* __restrict__ X, const float* __restrict__ G,
               const float* __restrict__ Bt, __half* __restrict__ Y)
{
    __shared__ float ss[8], sq[8];
    const int r = blockIdx.x, tid = threadIdx.x;
    const float* xr = X + (size_t)r * Dm;
    float4 v = *(const float4*)(xr + tid * 4);
    float s = v.x + v.y + v.z + v.w;
    float q = v.x*v.x + v.y*v.y + v.z*v.z + v.w*v.w;
#pragma unroll
    for (int off = 16; off >= 1; off >>= 1) {
        s += __shfl_xor_sync(0xffffffffu, s, off);
        q += __shfl_xor_sync(0xffffffffu, q, off);
    }
    if ((tid & 31) == 0) { ss[tid >> 5] = s; sq[tid >> 5] = q; }
    __syncthreads();
    float ts = 0.f, tq = 0.f;
#pragma unroll
    for (int w = 0; w < 8; w++) { ts += ss[w]; tq += sq[w]; }
    const float mu   = ts * (1.0f / Dm);
    const float var  = tq * (1.0f / Dm) - mu * mu;
    const float rstd = rsqrtf(var + 1e-5f);
    float4 g4 = *(const float4*)(G  + tid * 4);
    float4 b4 = *(const float4*)(Bt + tid * 4);
    uint2 o;
    o.x = pack_h2((v.x - mu) * rstd * g4.x + b4.x, (v.y - mu) * rstd * g4.y + b4.y);
    o.y = pack_h2((v.z - mu) * rstd * g4.z + b4.z, (v.w - mu) * rstd * g4.w + b4.w);
    *(uint2*)(Y + (size_t)r * Dm + tid * 4) = o;
}

// ---------------------------------------------------------------------------
// Weight convert+transpose: W[K,N] f32 -> WT [N,K] fp16
// ---------------------------------------------------------------------------
__global__ __launch_bounds__(256)
void wconv_kernel(const float* __restrict__ W, __half* __restrict__ Th,
                  int K, int N)
{
    __shared__ float t[32][33];
    const int n0 = blockIdx.x * 32, k0 = blockIdx.y * 32;
    const int tx = threadIdx.x, ty = threadIdx.y;
#pragma unroll
    for (int i = 0; i < 4; i++)
        t[ty + i*8][tx] = W[(size_t)(k0 + ty + i*8) * N + n0 + tx];
    __syncthreads();
#pragma unroll
    for (int i = 0; i < 4; i++) {
        const int r = ty + i*8;
        Th[(size_t)(n0 + r) * K + k0 + tx] = __float2half(t[tx][r]);
    }
}

// ---------------------------------------------------------------------------
// HMMA fp16 single-product GEMM: C[M,N] = A[M,K] @ Wh[K,N] + bias
// CTA tile 128x128, K-chunk 64, 3-stage cp.async pipeline (32KB/stage),
// 2 CTAs/SM. 8 warps as 2(M)x4(N); warp tile 64x32.
// MODE: 1 = bias+GELU -> fp16, 2 = bias+residual -> f32,
//       3 = bias -> fp16 scatter to [B,H,S,64], target by n0>>10
// ---------------------------------------------------------------------------
#define TMq 128
#define TNq 128
#define TILE_B   16384               // one tensor tile (128 x 128B)
#define STG_BYTES (2*TILE_B)         // A, B = 32768
#define GEMM_SMEM (3*STG_BYTES)      // 98304 (x2 CTAs = 196KB/SM)
#define OFF_BH (TILE_B)

__device__ __forceinline__ void load_stage(
    uint32_t st, const __half* __restrict__ A, const __half* __restrict__ Bh,
    int m0, int n0, int kc, int K, int tid)
{
#pragma unroll
    for (int j = 0; j < 4; j++) {          // 128 rows x 8 chunks of 16B
        const int i = tid + j * 256;
        const int r = i >> 3, c = i & 7;
        const uint32_t off = SWZ((uint32_t)(r * 128 + c * 16));
        cpa16(st + off,          A  + (size_t)(m0 + r) * K + kc + c * 8);
        cpa16(st + OFF_BH + off, Bh + (size_t)(n0 + r) * K + kc + c * 8);
    }
}

template<int MODE>
__global__ __launch_bounds__(256, 2)
void gemm_hmma(const __half* __restrict__ A, const __half* __restrict__ Bh,
               const float* __restrict__ bias, const float* __restrict__ res,
               float* __restrict__ Cf, __half* __restrict__ C16,
               __half* __restrict__ Ck, __half* __restrict__ Cv,
               int N, int K)
{
    extern __shared__ __align__(1024) char smem[];
    const uint32_t sb = s2u(smem);
    const int tid = threadIdx.x, lane = tid & 31, warp = tid >> 5;
    const int wm = warp >> 2, wn = warp & 3;
    const int m0 = blockIdx.y * TMq, n0 = blockIdx.x * TNq;

    float acc[4][4][4];
#pragma unroll
    for (int a = 0; a < 4; a++)
#pragma unroll
        for (int b = 0; b < 4; b++)
#pragma unroll
            for (int c = 0; c < 4; c++) acc[a][b][c] = 0.f;

    uint32_t rowA[4], rowB[4];
#pragma unroll
    for (int mf = 0; mf < 4; mf++)
        rowA[mf] = (uint32_t)((wm*64 + mf*16 + (lane & 15)) * 128 + (lane >> 4) * 16);
#pragma unroll
    for (int nf = 0; nf < 4; nf++)
        rowB[nf] = (uint32_t)((wn*32 + nf*8 + (lane & 7)) * 128 + ((lane >> 3) & 1) * 16);

    const int NC = K >> 6;
    load_stage(sb,               A, Bh, m0, n0, 0,   K, tid); cpa_commit();
    load_stage(sb +   STG_BYTES, A, Bh, m0, n0, 64,  K, tid); cpa_commit();
    load_stage(sb + 2*STG_BYTES, A, Bh, m0, n0, 128, K, tid); cpa_commit();

    int stg = 0;
    for (int c = 0; c < NC; c++) {
        const int rem = NC - 1 - c;
        if (rem >= 2)      cpa_wait<2>();
        else if (rem == 1) cpa_wait<1>();
        else               cpa_wait<0>();
        __syncthreads();

        const uint32_t stA = sb + stg * STG_BYTES;
#pragma unroll
        for (int ks = 0; ks < 4; ks++) {
            const uint32_t ko = ks * 32;
            uint32_t ah[4][4], bh[4][2];
#pragma unroll
            for (int mf = 0; mf < 4; mf++)
                ldsm4(ah[mf], stA + SWZ(rowA[mf] + ko));
#pragma unroll
            for (int nf = 0; nf < 4; nf++)
                ldsm2(bh[nf], stA + OFF_BH + SWZ(rowB[nf] + ko));
#pragma unroll
            for (int mf = 0; mf < 4; mf++)
#pragma unroll
                for (int nf = 0; nf < 4; nf++)
                    mma_f16(acc[mf][nf], ah[mf], bh[nf]);
        }
        __syncthreads();
        if (c + 3 < NC) {
            load_stage(stA, A, Bh, m0, n0, (c + 3) * 64, K, tid);
            cpa_commit();
        }
        stg = (stg + 1 == 3) ? 0 : stg + 1;
    }

    const int qr = lane >> 2, qc = (lane & 3) * 2;
    __half* Oh = nullptr;
    if (MODE == 3) {
        const int which = n0 >> 10;
        Oh = (which == 0) ? C16 : (which == 1) ? Ck : Cv;
    }
#pragma unroll
    for (int mf = 0; mf < 4; mf++) {
#pragma unroll
        for (int nf = 0; nf < 4; nf++) {
            const int row = m0 + wm*64 + mf*16 + qr;
            const int col = n0 + wn*32 + nf*8 + qc;
            float2 bv = *(const float2*)(bias + col);
            float x0 = acc[mf][nf][0] + bv.x, x1 = acc[mf][nf][1] + bv.y;
            float y0 = acc[mf][nf][2] + bv.x, y1 = acc[mf][nf][3] + bv.y;
            if (MODE == 1) {
                x0 *= normcdff(x0); x1 *= normcdff(x1);
                y0 *= normcdff(y0); y1 *= normcdff(y1);
                const size_t o0 = (size_t)row * N + col;
                const size_t o1 = (size_t)(row + 8) * N + col;
                *(uint32_t*)(C16 + o0) = pack_h2(x0, x1);
                *(uint32_t*)(C16 + o1) = pack_h2(y0, y1);
            } else if (MODE == 2) {
                const size_t o0 = (size_t)row * N + col;
                const size_t o1 = (size_t)(row + 8) * N + col;
                float2 r0 = *(const float2*)(res + o0);
                float2 r1 = *(const float2*)(res + o1);
                *(float2*)(Cf + o0) = make_float2(x0 + r0.x, x1 + r0.y);
                *(float2*)(Cf + o1) = make_float2(y0 + r1.x, y1 + r1.y);
            } else {
                const int coll = col & 1023;
                const int h = coll >> 6, hd = coll & 63;
                const int b0r = row >> 11, s0 = row & 2047;
                const int b1r = (row + 8) >> 11, s1 = (row + 8) & 2047;
                const size_t o0 = ((size_t)(b0r * Hh + h) * Sq + s0) * HDm + hd;
                const size_t o1 = ((size_t)(b1r * Hh + h) * Sq + s1) * HDm + hd;
                *(uint32_t*)(Oh + o0) = pack_h2(x0, x1);
                *(uint32_t*)(Oh + o1) = pack_h2(y0, y1);
            }
        }
    }
}

// ---------------------------------------------------------------------------
// HMMA flash attention: single-product QK^T, 2-product (P split) PV.
// CTA: 128 queries x one (b,h); 8 warps; KV tiles of 64; 3-stage pipeline.
// Q/K/V fp16 [BH, S, 64]; output fp16 [B,S,D] token-major.
// ---------------------------------------------------------------------------
#define ATT_QB   16384                    // Q tile (128 x 128B)
#define ATT_KVB  8192                     // one KV tensor tile (64 x 128B)
#define ATT_STG  (2*ATT_KVB)              // kh, vh = 16384
#define ATT_SMEM (ATT_QB + 3*ATT_STG)     // 65536 (x2 CTAs = 128KB/SM)

__device__ __forceinline__ void att_load_stage(
    uint32_t st, const __half* __restrict__ Kh, const __half* __restrict__ Vh,
    size_t tb, int kv0, int tid)
{
#pragma unroll
    for (int j = 0; j < 4; j++) {
        const int i = tid + j * 256;           // 0..1023
        const int t = i >> 9;                  // 0=K, 1=V
        const int r = (i >> 3) & 63;
        const int c = i & 7;
        const __half* src = t ? Vh : Kh;
        cpa16(st + t * ATT_KVB + SWZ((uint32_t)(r * 128 + c * 16)),
              src + tb + (size_t)(kv0 + r) * HDm + c * 8);
    }
}

__global__ __launch_bounds__(256, 2)
void attn_hmma(const __half* __restrict__ Qh_, const __half* __restrict__ Kh_,
               const __half* __restrict__ Vh_, __half* __restrict__ O)
{
    extern __shared__ __align__(1024) char smem[];
    const uint32_t sb = s2u(smem);
    const int tid = threadIdx.x, lane = tid & 31, warp = tid >> 5;
    const int bh = blockIdx.y;
    const int q0 = blockIdx.x * 128;
    const size_t tb = (size_t)bh * Sq * HDm;

    att_load_stage(sb + ATT_QB,             Kh_, Vh_, tb, 0,   tid); cpa_commit();
    att_load_stage(sb + ATT_QB +   ATT_STG, Kh_, Vh_, tb, 64,  tid); cpa_commit();
    att_load_stage(sb + ATT_QB + 2*ATT_STG, Kh_, Vh_, tb, 128, tid); cpa_commit();
#pragma unroll
    for (int j = 0; j < 4; j++) {
        const int i = tid + j * 256;           // 0..1023
        const int r = i >> 3, c = i & 7;
        cpa16(sb + SWZ((uint32_t)(r * 128 + c * 16)),
              Qh_ + tb + (size_t)(q0 + r) * HDm + c * 8);
    }
    cpa_commit();
    cpa_wait<0>();
    __syncthreads();

    uint32_t qf[4][4];
    {
        const uint32_t qrow = (uint32_t)((16*warp + (lane & 15)) * 128 + (lane >> 4) * 16);
#pragma unroll
        for (int kf = 0; kf < 4; kf++)
            ldsm4(qf[kf], sb + SWZ(qrow + kf * 32));
    }

    float acco[8][4];
#pragma unroll
    for (int nf = 0; nf < 8; nf++)
#pragma unroll
        for (int c = 0; c < 4; c++) acco[nf][c] = 0.f;
    float m0v = -1e30f, m1v = -1e30f, l0v = 0.f, l1v = 0.f;

    const int NT = Sq / 64;   // 32
    int stg = 0;
    for (int c = 0; c < NT; c++) {
        const int rem = NT - 1 - c;
        if (rem >= 2)      cpa_wait<2>();
        else if (rem == 1) cpa_wait<1>();
        else               cpa_wait<0>();
        __syncthreads();

        const uint32_t stb = sb + ATT_QB + stg * ATT_STG;

        float accs[8][4];
#pragma unroll
        for (int nf = 0; nf < 8; nf++)
#pragma unroll
            for (int q4 = 0; q4 < 4; q4++) accs[nf][q4] = 0.f;

#pragma unroll
        for (int kf = 0; kf < 4; kf++) {
            uint32_t bhf[4][4];
#pragma unroll
            for (int nfp = 0; nfp < 4; nfp++) {
                const uint32_t row = (uint32_t)(16*nfp + ((lane >> 4) << 3) + (lane & 7));
                const uint32_t kb  = (uint32_t)(kf * 32 + ((lane >> 3) & 1) * 16);
                ldsm4(bhf[nfp], stb + SWZ(row * 128 + kb));
            }
#pragma unroll
            for (int nfp = 0; nfp < 4; nfp++) {
                mma_f16(accs[2*nfp],   qf[kf], &bhf[nfp][0]);
                mma_f16(accs[2*nfp+1], qf[kf], &bhf[nfp][2]);
            }
        }

        float mx0 = -1e30f, mx1 = -1e30f;
#pragma unroll
        for (int nf = 0; nf < 8; nf++) {
            mx0 = fmaxf(mx0, fmaxf(accs[nf][0], accs[nf][1]));
            mx1 = fmaxf(mx1, fmaxf(accs[nf][2], accs[nf][3]));
        }
        mx0 *= 0.125f; mx1 *= 0.125f;
#pragma unroll
        for (int off = 1; off <= 2; off <<= 1) {
            mx0 = fmaxf(mx0, __shfl_xor_sync(0xffffffffu, mx0, off));
            mx1 = fmaxf(mx1, __shfl_xor_sync(0xffffffffu, mx1, off));
        }
        const float mn0 = fmaxf(m0v, mx0), mn1 = fmaxf(m1v, mx1);
        const float cr0 = __expf(m0v - mn0), cr1 = __expf(m1v - mn1);
        float sum0 = 0.f, sum1 = 0.f;
#pragma unroll
        for (int nf = 0; nf < 8; nf++) {
            float p0 = __expf(fmaf(accs[nf][0], 0.125f, -mn0));
            float p1 = __expf(fmaf(accs[nf][1], 0.125f, -mn0));
            float p2 = __expf(fmaf(accs[nf][2], 0.125f, -mn1));
            float p3 = __expf(fmaf(accs[nf][3], 0.125f, -mn1));
            accs[nf][0] = p0; accs[nf][1] = p1; accs[nf][2] = p2; accs[nf][3] = p3;
            sum0 += p0 + p1; sum1 += p2 + p3;
        }
#pragma unroll
        for (int off = 1; off <= 2; off <<= 1) {
            sum0 += __shfl_xor_sync(0xffffffffu, sum0, off);
            sum1 += __shfl_xor_sync(0xffffffffu, sum1, off);
        }
        l0v = l0v * cr0 + sum0;  m0v = mn0;
        l1v = l1v * cr1 + sum1;  m1v = mn1;
#pragma unroll
        for (int nf = 0; nf < 8; nf++) {
            acco[nf][0] *= cr0; acco[nf][1] *= cr0;
            acco[nf][2] *= cr1; acco[nf][3] *= cr1;
        }

#pragma unroll
        for (int kf2 = 0; kf2 < 4; kf2++) {
            uint32_t aPh[4], aPl[4];
            split_pack2(accs[2*kf2][0],   accs[2*kf2][1],   aPh[0], aPl[0]);
            split_pack2(accs[2*kf2][2],   accs[2*kf2][3],   aPh[1], aPl[1]);
            split_pack2(accs[2*kf2+1][0], accs[2*kf2+1][1], aPh[2], aPl[2]);
            split_pack2(accs[2*kf2+1][2], accs[2*kf2+1][3], aPh[3], aPl[3]);
#pragma unroll
            for (int nfp2 = 0; nfp2 < 4; nfp2++) {
                const uint32_t row  = (uint32_t)(16*kf2 + ((lane >> 3) & 1) * 8 + (lane & 7));
                const uint32_t colb = (uint32_t)(nfp2 * 32 + (lane >> 4) * 16);
                uint32_t vhf[4];
                ldsm4t(vhf, stb + ATT_KVB + SWZ(row * 128 + colb));
                mma_f16(acco[2*nfp2],   aPh, &vhf[0]);
                mma_f16(acco[2*nfp2],   aPl, &vhf[0]);
                mma_f16(acco[2*nfp2+1], aPh, &vhf[2]);
                mma_f16(acco[2*nfp2+1], aPl, &vhf[2]);
            }
        }

        __syncthreads();
        if (c + 3 < NT) {
            att_load_stage(sb + ATT_QB + stg * ATT_STG, Kh_, Vh_, tb, (c + 3) * 64, tid);
            cpa_commit();
        }
        stg = (stg + 1 == 3) ? 0 : stg + 1;
    }

    const float inv0 = 1.f / l0v, inv1 = 1.f / l1v;
    const int b = bh >> 4, h = bh & 15;
    const int s0 = q0 + warp * 16 + (lane >> 2), s1 = s0 + 8;
#pragma unroll
    for (int nf = 0; nf < 8; nf++) {
        const int col = h * HDm + nf * 8 + (lane & 3) * 2;
        const size_t o0 = (size_t)(b * Sq + s0) * Dm + col;
        const size_t o1 = (size_t)(b * Sq + s1) * Dm + col;
        *(uint32_t*)(O + o0) = pack_h2(acco[nf][0] * inv0, acco[nf][1] * inv0);
        *(uint32_t*)(O + o1) = pack_h2(acco[nf][2] * inv1, acco[nf][3] * inv1);
    }
}

// ---------------------------------------------------------------------------
extern "C" void kernel_launch(void* const* d_in, const int* in_sizes, int n_in,
                              void* d_out, int out_size)
{
    const float* x    = (const float*)d_in[0];
    const float* Wq   = (const float*)d_in[1];
    const float* bq   = (const float*)d_in[2];
    const float* Wk   = (const float*)d_in[3];
    const float* bk   = (const float*)d_in[4];
    const float* Wv   = (const float*)d_in[5];
    const float* bv   = (const float*)d_in[6];
    const float* Wo   = (const float*)d_in[7];
    const float* bo   = (const float*)d_in[8];
    const float* ln1g = (const float*)d_in[9];
    const float* ln1b = (const float*)d_in[10];
    const float* ln2g = (const float*)d_in[11];
    const float* ln2b = (const float*)d_in[12];
    const float* W1   = (const float*)d_in[13];
    const float* b1   = (const float*)d_in[14];
    const float* W2   = (const float*)d_in[15];
    const float* b2   = (const float*)d_in[16];
    float* out = (float*)d_out;

    float *x2, *bqkv;
    __half *a16, *h16, *q16, *k16, *v16;
    __half *wqkv, *wo, *w1, *w2;
    cudaGetSymbolAddress((void**)&x2,   g_x2);
    cudaGetSymbolAddress((void**)&bqkv, g_bqkv);
    cudaGetSymbolAddress((void**)&a16,  g_a);
    cudaGetSymbolAddress((void**)&h16,  g_h);
    cudaGetSymbolAddress((void**)&q16,  g_q);
    cudaGetSymbolAddress((void**)&k16,  g_k);
    cudaGetSymbolAddress((void**)&v16,  g_v);
    cudaGetSymbolAddress((void**)&wqkv, g_wqkv);
    cudaGetSymbolAddress((void**)&wo,   g_wo);
    cudaGetSymbolAddress((void**)&w1,   g_w1);
    cudaGetSymbolAddress((void**)&w2,   g_w2);

    cudaFuncSetAttribute(attn_hmma, cudaFuncAttributeMaxDynamicSharedMemorySize, ATT_SMEM);
    cudaFuncSetAttribute(gemm_hmma<1>, cudaFuncAttributeMaxDynamicSharedMemorySize, GEMM_SMEM);
    cudaFuncSetAttribute(gemm_hmma<2>, cudaFuncAttributeMaxDynamicSharedMemorySize, GEMM_SMEM);
    cudaFuncSetAttribute(gemm_hmma<3>, cudaFuncAttributeMaxDynamicSharedMemorySize, GEMM_SMEM);

    const dim3 blk(256);
    const dim3 wblk(32, 8);
    const dim3 gQKV(3*Dm / TNq, NTOK / TMq);  // (24, 64)
    const dim3 gP  (Dm   / TNq, NTOK / TMq);  // (8, 64)
    const dim3 gF1 (DFm  / TNq, NTOK / TMq);  // (32, 64)

    // 0) weight convert + transpose (fp16, [N,K]); QKV concatenated
    wconv_kernel<<<dim3(Dm/32,  Dm/32),  wblk>>>(Wq, wqkv,            Dm,  Dm);
    wconv_kernel<<<dim3(Dm/32,  Dm/32),  wblk>>>(Wk, wqkv + Dm*Dm,    Dm,  Dm);
    wconv_kernel<<<dim3(Dm/32,  Dm/32),  wblk>>>(Wv, wqkv + 2*Dm*Dm,  Dm,  Dm);
    wconv_kernel<<<dim3(Dm/32,  Dm/32),  wblk>>>(Wo, wo,              Dm,  Dm);
    wconv_kernel<<<dim3(DFm/32, Dm/32),  wblk>>>(W1, w1,              Dm,  DFm);
    wconv_kernel<<<dim3(Dm/32,  DFm/32), wblk>>>(W2, w2,              DFm, Dm);
    cudaMemcpyAsync(bqkv,        bq, Dm*sizeof(float), cudaMemcpyDeviceToDevice);
    cudaMemcpyAsync(bqkv +   Dm, bk, Dm*sizeof(float), cudaMemcpyDeviceToDevice);
    cudaMemcpyAsync(bqkv + 2*Dm, bv, Dm*sizeof(float), cudaMemcpyDeviceToDevice);

    // 1) LN1 -> fp16
    ln_kernel<<<NTOK, blk>>>(x, ln1g, ln1b, a16);
    // 2) fused QKV projection -> fp16 scattered [B,H,S,64]
    gemm_hmma<3><<<gQKV, blk, GEMM_SMEM>>>(a16, wqkv, bqkv, nullptr, nullptr,
                                           q16, k16, v16, 3*Dm, Dm);
    // 3) attention -> fp16 [B,S,D]
    attn_hmma<<<dim3(Sq / 128, Bq * Hh), blk, ATT_SMEM>>>(q16, k16, v16, a16);
    // 4) output projection + residual -> x2 (f32)
    gemm_hmma<2><<<gP, blk, GEMM_SMEM>>>(a16, wo, bo, x, x2,
                                         nullptr, nullptr, nullptr, Dm, Dm);
    // 5) LN2 -> fp16
    ln_kernel<<<NTOK, blk>>>(x2, ln2g, ln2b, a16);
    // 6) FFN up + exact GELU -> fp16
    gemm_hmma<1><<<gF1, blk, GEMM_SMEM>>>(a16, w1, b1, nullptr, nullptr,
                                          h16, nullptr, nullptr, DFm, Dm);
    // 7) FFN down + residual -> out (f32)
    gemm_hmma<2><<<gP, blk, GEMM_SMEM>>>(h16, w2, b2, x2, out,
                                         nullptr, nullptr, nullptr, Dm, DFm);
}

// round 11
// speedup vs baseline: 2.5961x; 1.1553x over previous
#include <cuda_runtime.h>
#include <cuda_fp16.h>
#include <math.h>
#include <stdint.h>

// Problem constants
#define Bq   4
#define Sq   2048
#define Dm   1024
#define Hh   16
#define HDm  64
#define DFm  4096
#define NTOK (Bq*Sq)   // 8192
#define QKV_SZ (NTOK*Dm)

// ---------------------------------------------------------------------------
// Scratch (module-load allocated)
// ---------------------------------------------------------------------------
__device__ float g_x2 [NTOK*Dm];
__device__ float g_bqkv[3*Dm];

__device__ __half g_a  [NTOK*Dm];      // LN output / attention output (fp16)
__device__ __half g_h  [NTOK*DFm];     // FFN hidden (fp16)

__device__ __half g_q [QKV_SZ];
__device__ __half g_k [QKV_SZ];
__device__ __half g_v [QKV_SZ];

__device__ __half g_wqkv[3*Dm*Dm];     // fused QKV weights, [3072, 1024] K-major
__device__ __half g_wo [Dm*Dm];
__device__ __half g_w1 [Dm*DFm];
__device__ __half g_w2 [Dm*DFm];

// ---------------------------------------------------------------------------
// PTX helpers
// ---------------------------------------------------------------------------
__device__ __forceinline__ uint32_t s2u(const void* p) {
    uint32_t a;
    asm("{ .reg .u64 t; cvta.to.shared.u64 t, %1; cvt.u32.u64 %0, t; }"
        : "=r"(a) : "l"(p));
    return a;
}
__device__ __forceinline__ void cpa16(uint32_t d, const void* s) {
    asm volatile("cp.async.cg.shared.global [%0], [%1], 16;"
                 :: "r"(d), "l"(s) : "memory");
}
__device__ __forceinline__ void cpa_commit() {
    asm volatile("cp.async.commit_group;" ::: "memory");
}
template<int NN> __device__ __forceinline__ void cpa_wait() {
    asm volatile("cp.async.wait_group %0;" :: "n"(NN) : "memory");
}
__device__ __forceinline__ void ldsm4(uint32_t* r, uint32_t a) {
    asm volatile("ldmatrix.sync.aligned.m8n8.x4.shared.b16 {%0,%1,%2,%3}, [%4];"
                 : "=r"(r[0]), "=r"(r[1]), "=r"(r[2]), "=r"(r[3]) : "r"(a));
}
__device__ __forceinline__ void ldsm4t(uint32_t* r, uint32_t a) {
    asm volatile("ldmatrix.sync.aligned.m8n8.x4.trans.shared.b16 {%0,%1,%2,%3}, [%4];"
                 : "=r"(r[0]), "=r"(r[1]), "=r"(r[2]), "=r"(r[3]) : "r"(a));
}
__device__ __forceinline__ void mma_f16(float* d, const uint32_t* a, const uint32_t* b) {
    asm volatile(
        "mma.sync.aligned.m16n8k16.row.col.f32.f16.f16.f32 "
        "{%0,%1,%2,%3}, {%4,%5,%6,%7}, {%8,%9}, {%0,%1,%2,%3};"
        : "+f"(d[0]), "+f"(d[1]), "+f"(d[2]), "+f"(d[3])
        : "r"(a[0]), "r"(a[1]), "r"(a[2]), "r"(a[3]), "r"(b[0]), "r"(b[1]));
}

__device__ __forceinline__ uint32_t pack_h2(float x, float y) {
    __half2 h = __floats2half2_rn(x, y);
    return *(uint32_t*)&h;
}

#define SWZ(x) ((x) ^ (((x) >> 3) & 0x70))

// ---------------------------------------------------------------------------
// LayerNorm: one block per row, emits fp16
// ---------------------------------------------------------------------------
__global__ __launch_bounds__(256)
void ln_kernel(const float* __restrict__ X, const float* __restrict__ G,
               const float* __restrict__ Bt, __half* __restrict__ Y)
{
    __shared__ float ss[8], sq[8];
    const int r = blockIdx.x, tid = threadIdx.x;
    const float* xr = X + (size_t)r * Dm;
    float4 v = *(const float4*)(xr + tid * 4);
    float s = v.x + v.y + v.z + v.w;
    float q = v.x*v.x + v.y*v.y + v.z*v.z + v.w*v.w;
#pragma unroll
    for (int off = 16; off >= 1; off >>= 1) {
        s += __shfl_xor_sync(0xffffffffu, s, off);
        q += __shfl_xor_sync(0xffffffffu, q, off);
    }
    if ((tid & 31) == 0) { ss[tid >> 5] = s; sq[tid >> 5] = q; }
    __syncthreads();
    float ts = 0.f, tq = 0.f;
#pragma unroll
    for (int w = 0; w < 8; w++) { ts += ss[w]; tq += sq[w]; }
    const float mu   = ts * (1.0f / Dm);
    const float var  = tq * (1.0f / Dm) - mu * mu;
    const float rstd = rsqrtf(var + 1e-5f);
    float4 g4 = *(const float4*)(G  + tid * 4);
    float4 b4 = *(const float4*)(Bt + tid * 4);
    uint2 o;
    o.x = pack_h2((v.x - mu) * rstd * g4.x + b4.x, (v.y - mu) * rstd * g4.y + b4.y);
    o.y = pack_h2((v.z - mu) * rstd * g4.z + b4.z, (v.w - mu) * rstd * g4.w + b4.w);
    *(uint2*)(Y + (size_t)r * Dm + tid * 4) = o;
}

// ---------------------------------------------------------------------------
// Combined weight convert+transpose for ALL weights + QKV bias concat.
// Tile map: [0,1024) Wq, [1024,2048) Wk, [2048,3072) Wv, [3072,4096) Wo,
//           [4096,8192) W1, [8192,12288) W2, [12288,12291) bias copies.
// ---------------------------------------------------------------------------
__global__ __launch_bounds__(256)
void wconv_all(const float* __restrict__ Wq, const float* __restrict__ Wk,
               const float* __restrict__ Wv, const float* __restrict__ Wo,
               const float* __restrict__ W1, const float* __restrict__ W2,
               const float* __restrict__ bq, const float* __restrict__ bk,
               const float* __restrict__ bv,
               __half* __restrict__ wqkv, __half* __restrict__ wo,
               __half* __restrict__ w1, __half* __restrict__ w2,
               float* __restrict__ bqkv)
{
    const int id = blockIdx.x;
    const int tx = threadIdx.x, ty = threadIdx.y;
    if (id >= 12288) {
        const int w = id - 12288;
        const float* src = (w == 0) ? bq : (w == 1) ? bk : bv;
        const int t = ty * 32 + tx;
#pragma unroll
        for (int i = 0; i < 4; i++)
            bqkv[w * Dm + t + i * 256] = src[t + i * 256];
        return;
    }
    const float* W; __half* T; int K, N, tile0;
    if      (id < 1024) { W = Wq; T = wqkv;            K = Dm;  N = Dm;  tile0 = 0; }
    else if (id < 2048) { W = Wk; T = wqkv + Dm*Dm;    K = Dm;  N = Dm;  tile0 = 1024; }
    else if (id < 3072) { W = Wv; T = wqkv + 2*Dm*Dm;  K = Dm;  N = Dm;  tile0 = 2048; }
    else if (id < 4096) { W = Wo; T = wo;              K = Dm;  N = Dm;  tile0 = 3072; }
    else if (id < 8192) { W = W1; T = w1;              K = Dm;  N = DFm; tile0 = 4096; }
    else                { W = W2; T = w2;              K = DFm; N = Dm;  tile0 = 8192; }
    const int lid = id - tile0;
    const int ntx = N >> 5;
    const int n0 = (lid % ntx) * 32, k0 = (lid / ntx) * 32;

    __shared__ float t[32][33];
#pragma unroll
    for (int i = 0; i < 4; i++)
        t[ty + i*8][tx] = W[(size_t)(k0 + ty + i*8) * N + n0 + tx];
    __syncthreads();
#pragma unroll
    for (int i = 0; i < 4; i++) {
        const int r = ty + i*8;
        T[(size_t)(n0 + r) * K + k0 + tx] = __float2half(t[tx][r]);
    }
}

// ---------------------------------------------------------------------------
// HMMA fp16 single-product GEMM: C[M,N] = A[M,K] @ Wh[K,N] + bias
// CTA tile 128x128, K-chunk 64, 3-stage cp.async pipeline, 2 CTAs/SM.
// 8 warps as 2(M)x4(N); warp tile 64x32; B frags via ldsm4 (2 per issue).
// MODE: 1 = bias+GELU -> fp16, 2 = bias+residual -> f32,
//       3 = bias -> fp16 scatter to [B,H,S,64], target by n0>>10 (Q pre-scaled)
// ---------------------------------------------------------------------------
#define TMq 128
#define TNq 128
#define TILE_B   16384
#define STG_BYTES (2*TILE_B)         // 32768
#define GEMM_SMEM (3*STG_BYTES)      // 98304
#define OFF_BH (TILE_B)

__device__ __forceinline__ void load_stage(
    uint32_t st, const __half* __restrict__ A, const __half* __restrict__ Bh,
    int m0, int n0, int kc, int K, int tid)
{
#pragma unroll
    for (int j = 0; j < 4; j++) {
        const int i = tid + j * 256;
        const int r = i >> 3, c = i & 7;
        const uint32_t off = SWZ((uint32_t)(r * 128 + c * 16));
        cpa16(st + off,          A  + (size_t)(m0 + r) * K + kc + c * 8);
        cpa16(st + OFF_BH + off, Bh + (size_t)(n0 + r) * K + kc + c * 8);
    }
}

template<int MODE>
__global__ __launch_bounds__(256, 2)
void gemm_hmma(const __half* __restrict__ A, const __half* __restrict__ Bh,
               const float* __restrict__ bias, const float* __restrict__ res,
               float* __restrict__ Cf, __half* __restrict__ C16,
               __half* __restrict__ Ck, __half* __restrict__ Cv,
               int N, int K)
{
    extern __shared__ __align__(1024) char smem[];
    const uint32_t sb = s2u(smem);
    const int tid = threadIdx.x, lane = tid & 31, warp = tid >> 5;
    const int wm = warp >> 2, wn = warp & 3;
    const int m0 = blockIdx.y * TMq, n0 = blockIdx.x * TNq;

    float acc[4][4][4];
#pragma unroll
    for (int a = 0; a < 4; a++)
#pragma unroll
        for (int b = 0; b < 4; b++)
#pragma unroll
            for (int c = 0; c < 4; c++) acc[a][b][c] = 0.f;

    uint32_t rowA[4], rowB4[2];
#pragma unroll
    for (int mf = 0; mf < 4; mf++)
        rowA[mf] = (uint32_t)((wm*64 + mf*16 + (lane & 15)) * 128 + (lane >> 4) * 16);
#pragma unroll
    for (int nfp = 0; nfp < 2; nfp++)
        rowB4[nfp] = (uint32_t)((wn*32 + nfp*16 + ((lane >> 4) << 3) + (lane & 7)) * 128
                                + ((lane >> 3) & 1) * 16);

    const int NC = K >> 6;
    load_stage(sb,               A, Bh, m0, n0, 0,   K, tid); cpa_commit();
    load_stage(sb +   STG_BYTES, A, Bh, m0, n0, 64,  K, tid); cpa_commit();
    load_stage(sb + 2*STG_BYTES, A, Bh, m0, n0, 128, K, tid); cpa_commit();

    int stg = 0;
    for (int c = 0; c < NC; c++) {
        const int rem = NC - 1 - c;
        if (rem >= 2)      cpa_wait<2>();
        else if (rem == 1) cpa_wait<1>();
        else               cpa_wait<0>();
        __syncthreads();

        const uint32_t stA = sb + stg * STG_BYTES;
#pragma unroll
        for (int ks = 0; ks < 4; ks++) {
            const uint32_t ko = ks * 32;
            uint32_t ah[4][4], bh[2][4];
#pragma unroll
            for (int mf = 0; mf < 4; mf++)
                ldsm4(ah[mf], stA + SWZ(rowA[mf] + ko));
#pragma unroll
            for (int nfp = 0; nfp < 2; nfp++)
                ldsm4(bh[nfp], stA + OFF_BH + SWZ(rowB4[nfp] + ko));
#pragma unroll
            for (int mf = 0; mf < 4; mf++) {
                mma_f16(acc[mf][0], ah[mf], &bh[0][0]);
                mma_f16(acc[mf][1], ah[mf], &bh[0][2]);
                mma_f16(acc[mf][2], ah[mf], &bh[1][0]);
                mma_f16(acc[mf][3], ah[mf], &bh[1][2]);
            }
        }
        __syncthreads();
        if (c + 3 < NC) {
            load_stage(stA, A, Bh, m0, n0, (c + 3) * 64, K, tid);
            cpa_commit();
        }
        stg = (stg + 1 == 3) ? 0 : stg + 1;
    }

    const int qr = lane >> 2, qc = (lane & 3) * 2;
    __half* Oh = nullptr;
    float qsc = 1.0f;
    if (MODE == 3) {
        const int which = n0 >> 10;
        Oh = (which == 0) ? C16 : (which == 1) ? Ck : Cv;
        if (which == 0) qsc = 0.125f;   // fold softmax scale into Q (exact pow2)
    }
#pragma unroll
    for (int mf = 0; mf < 4; mf++) {
#pragma unroll
        for (int nf = 0; nf < 4; nf++) {
            const int row = m0 + wm*64 + mf*16 + qr;
            const int col = n0 + wn*32 + nf*8 + qc;
            float2 bv = *(const float2*)(bias + col);
            float x0 = acc[mf][nf][0] + bv.x, x1 = acc[mf][nf][1] + bv.y;
            float y0 = acc[mf][nf][2] + bv.x, y1 = acc[mf][nf][3] + bv.y;
            if (MODE == 1) {
                x0 *= normcdff(x0); x1 *= normcdff(x1);
                y0 *= normcdff(y0); y1 *= normcdff(y1);
                const size_t o0 = (size_t)row * N + col;
                const size_t o1 = (size_t)(row + 8) * N + col;
                *(uint32_t*)(C16 + o0) = pack_h2(x0, x1);
                *(uint32_t*)(C16 + o1) = pack_h2(y0, y1);
            } else if (MODE == 2) {
                const size_t o0 = (size_t)row * N + col;
                const size_t o1 = (size_t)(row + 8) * N + col;
                float2 r0 = *(const float2*)(res + o0);
                float2 r1 = *(const float2*)(res + o1);
                *(float2*)(Cf + o0) = make_float2(x0 + r0.x, x1 + r0.y);
                *(float2*)(Cf + o1) = make_float2(y0 + r1.x, y1 + r1.y);
            } else {
                const int coll = col & 1023;
                const int h = coll >> 6, hd = coll & 63;
                const int b0r = row >> 11, s0 = row & 2047;
                const int b1r = (row + 8) >> 11, s1 = (row + 8) & 2047;
                const size_t o0 = ((size_t)(b0r * Hh + h) * Sq + s0) * HDm + hd;
                const size_t o1 = ((size_t)(b1r * Hh + h) * Sq + s1) * HDm + hd;
                *(uint32_t*)(Oh + o0) = pack_h2(x0 * qsc, x1 * qsc);
                *(uint32_t*)(Oh + o1) = pack_h2(y0 * qsc, y1 * qsc);
            }
        }
    }
}

// ---------------------------------------------------------------------------
// HMMA flash attention: single-product QK^T and PV (Q pre-scaled by 1/8).
// CTA: 128 queries x one (b,h); 8 warps; KV tiles of 64; 3-stage pipeline.
// ---------------------------------------------------------------------------
#define ATT_QB   16384
#define ATT_KVB  8192
#define ATT_STG  (2*ATT_KVB)              // 16384
#define ATT_SMEM (ATT_QB + 3*ATT_STG)     // 65536

__device__ __forceinline__ void att_load_stage(
    uint32_t st, const __half* __restrict__ Kh, const __half* __restrict__ Vh,
    size_t tb, int kv0, int tid)
{
#pragma unroll
    for (int j = 0; j < 4; j++) {
        const int i = tid + j * 256;
        const int t = i >> 9;
        const int r = (i >> 3) & 63;
        const int c = i & 7;
        const __half* src = t ? Vh : Kh;
        cpa16(st + t * ATT_KVB + SWZ((uint32_t)(r * 128 + c * 16)),
              src + tb + (size_t)(kv0 + r) * HDm + c * 8);
    }
}

__global__ __launch_bounds__(256, 2)
void attn_hmma(const __half* __restrict__ Qh_, const __half* __restrict__ Kh_,
               const __half* __restrict__ Vh_, __half* __restrict__ O)
{
    extern __shared__ __align__(1024) char smem[];
    const uint32_t sb = s2u(smem);
    const int tid = threadIdx.x, lane = tid & 31, warp = tid >> 5;
    const int bh = blockIdx.y;
    const int q0 = blockIdx.x * 128;
    const size_t tb = (size_t)bh * Sq * HDm;

    att_load_stage(sb + ATT_QB,             Kh_, Vh_, tb, 0,   tid); cpa_commit();
    att_load_stage(sb + ATT_QB +   ATT_STG, Kh_, Vh_, tb, 64,  tid); cpa_commit();
    att_load_stage(sb + ATT_QB + 2*ATT_STG, Kh_, Vh_, tb, 128, tid); cpa_commit();
#pragma unroll
    for (int j = 0; j < 4; j++) {
        const int i = tid + j * 256;
        const int r = i >> 3, c = i & 7;
        cpa16(sb + SWZ((uint32_t)(r * 128 + c * 16)),
              Qh_ + tb + (size_t)(q0 + r) * HDm + c * 8);
    }
    cpa_commit();
    cpa_wait<0>();
    __syncthreads();

    uint32_t qf[4][4];
    {
        const uint32_t qrow = (uint32_t)((16*warp + (lane & 15)) * 128 + (lane >> 4) * 16);
#pragma unroll
        for (int kf = 0; kf < 4; kf++)
            ldsm4(qf[kf], sb + SWZ(qrow + kf * 32));
    }

    float acco[8][4];
#pragma unroll
    for (int nf = 0; nf < 8; nf++)
#pragma unroll
        for (int c = 0; c < 4; c++) acco[nf][c] = 0.f;
    float m0v = -1e30f, m1v = -1e30f, l0v = 0.f, l1v = 0.f;

    const int NT = Sq / 64;   // 32
    int stg = 0;
    for (int c = 0; c < NT; c++) {
        const int rem = NT - 1 - c;
        if (rem >= 2)      cpa_wait<2>();
        else if (rem == 1) cpa_wait<1>();
        else               cpa_wait<0>();
        __syncthreads();

        const uint32_t stb = sb + ATT_QB + stg * ATT_STG;

        float accs[8][4];
#pragma unroll
        for (int nf = 0; nf < 8; nf++)
#pragma unroll
            for (int q4 = 0; q4 < 4; q4++) accs[nf][q4] = 0.f;

#pragma unroll
        for (int kf = 0; kf < 4; kf++) {
            uint32_t bhf[4][4];
#pragma unroll
            for (int nfp = 0; nfp < 4; nfp++) {
                const uint32_t row = (uint32_t)(16*nfp + ((lane >> 4) << 3) + (lane & 7));
                const uint32_t kb  = (uint32_t)(kf * 32 + ((lane >> 3) & 1) * 16);
                ldsm4(bhf[nfp], stb + SWZ(row * 128 + kb));
            }
#pragma unroll
            for (int nfp = 0; nfp < 4; nfp++) {
                mma_f16(accs[2*nfp],   qf[kf], &bhf[nfp][0]);
                mma_f16(accs[2*nfp+1], qf[kf], &bhf[nfp][2]);
            }
        }

        // online softmax (Q pre-scaled; scores already in final domain)
        float mx0 = -1e30f, mx1 = -1e30f;
#pragma unroll
        for (int nf = 0; nf < 8; nf++) {
            mx0 = fmaxf(mx0, fmaxf(accs[nf][0], accs[nf][1]));
            mx1 = fmaxf(mx1, fmaxf(accs[nf][2], accs[nf][3]));
        }
#pragma unroll
        for (int off = 1; off <= 2; off <<= 1) {
            mx0 = fmaxf(mx0, __shfl_xor_sync(0xffffffffu, mx0, off));
            mx1 = fmaxf(mx1, __shfl_xor_sync(0xffffffffu, mx1, off));
        }
        const float mn0 = fmaxf(m0v, mx0), mn1 = fmaxf(m1v, mx1);
        const float cr0 = __expf(m0v - mn0), cr1 = __expf(m1v - mn1);
        float sum0 = 0.f, sum1 = 0.f;
#pragma unroll
        for (int nf = 0; nf < 8; nf++) {
            float p0 = __expf(accs[nf][0] - mn0);
            float p1 = __expf(accs[nf][1] - mn0);
            float p2 = __expf(accs[nf][2] - mn1);
            float p3 = __expf(accs[nf][3] - mn1);
            accs[nf][0] = p0; accs[nf][1] = p1; accs[nf][2] = p2; accs[nf][3] = p3;
            sum0 += p0 + p1; sum1 += p2 + p3;
        }
#pragma unroll
        for (int off = 1; off <= 2; off <<= 1) {
            sum0 += __shfl_xor_sync(0xffffffffu, sum0, off);
            sum1 += __shfl_xor_sync(0xffffffffu, sum1, off);
        }
        l0v = l0v * cr0 + sum0;  m0v = mn0;
        l1v = l1v * cr1 + sum1;  m1v = mn1;
#pragma unroll
        for (int nf = 0; nf < 8; nf++) {
            acco[nf][0] *= cr0; acco[nf][1] *= cr0;
            acco[nf][2] *= cr1; acco[nf][3] *= cr1;
        }

        // O += P V (single product, P rounded to fp16)
#pragma unroll
        for (int kf2 = 0; kf2 < 4; kf2++) {
            uint32_t aP[4];
            aP[0] = pack_h2(accs[2*kf2][0],   accs[2*kf2][1]);
            aP[1] = pack_h2(accs[2*kf2][2],   accs[2*kf2][3]);
            aP[2] = pack_h2(accs[2*kf2+1][0], accs[2*kf2+1][1]);
            aP[3] = pack_h2(accs[2*kf2+1][2], accs[2*kf2+1][3]);
#pragma unroll
            for (int nfp2 = 0; nfp2 < 4; nfp2++) {
                const uint32_t row  = (uint32_t)(16*kf2 + ((lane >> 3) & 1) * 8 + (lane & 7));
                const uint32_t colb = (uint32_t)(nfp2 * 32 + (lane >> 4) * 16);
                uint32_t vhf[4];
                ldsm4t(vhf, stb + ATT_KVB + SWZ(row * 128 + colb));
                mma_f16(acco[2*nfp2],   aP, &vhf[0]);
                mma_f16(acco[2*nfp2+1], aP, &vhf[2]);
            }
        }

        __syncthreads();
        if (c + 3 < NT) {
            att_load_stage(sb + ATT_QB + stg * ATT_STG, Kh_, Vh_, tb, (c + 3) * 64, tid);
            cpa_commit();
        }
        stg = (stg + 1 == 3) ? 0 : stg + 1;
    }

    const float inv0 = 1.f / l0v, inv1 = 1.f / l1v;
    const int b = bh >> 4, h = bh & 15;
    const int s0 = q0 + warp * 16 + (lane >> 2), s1 = s0 + 8;
#pragma unroll
    for (int nf = 0; nf < 8; nf++) {
        const int col = h * HDm + nf * 8 + (lane & 3) * 2;
        const size_t o0 = (size_t)(b * Sq + s0) * Dm + col;
        const size_t o1 = (size_t)(b * Sq + s1) * Dm + col;
        *(uint32_t*)(O + o0) = pack_h2(acco[nf][0] * inv0, acco[nf][1] * inv0);
        *(uint32_t*)(O + o1) = pack_h2(acco[nf][2] * inv1, acco[nf][3] * inv1);
    }
}

// ---------------------------------------------------------------------------
extern "C" void kernel_launch(void* const* d_in, const int* in_sizes, int n_in,
                              void* d_out, int out_size)
{
    const float* x    = (const float*)d_in[0];
    const float* Wq   = (const float*)d_in[1];
    const float* bq   = (const float*)d_in[2];
    const float* Wk   = (const float*)d_in[3];
    const float* bk   = (const float*)d_in[4];
    const float* Wv   = (const float*)d_in[5];
    const float* bv   = (const float*)d_in[6];
    const float* Wo   = (const float*)d_in[7];
    const float* bo   = (const float*)d_in[8];
    const float* ln1g = (const float*)d_in[9];
    const float* ln1b = (const float*)d_in[10];
    const float* ln2g = (const float*)d_in[11];
    const float* ln2b = (const float*)d_in[12];
    const float* W1   = (const float*)d_in[13];
    const float* b1   = (const float*)d_in[14];
    const float* W2   = (const float*)d_in[15];
    const float* b2   = (const float*)d_in[16];
    float* out = (float*)d_out;

    float *x2, *bqkv;
    __half *a16, *h16, *q16, *k16, *v16;
    __half *wqkv, *wo, *w1, *w2;
    cudaGetSymbolAddress((void**)&x2,   g_x2);
    cudaGetSymbolAddress((void**)&bqkv, g_bqkv);
    cudaGetSymbolAddress((void**)&a16,  g_a);
    cudaGetSymbolAddress((void**)&h16,  g_h);
    cudaGetSymbolAddress((void**)&q16,  g_q);
    cudaGetSymbolAddress((void**)&k16,  g_k);
    cudaGetSymbolAddress((void**)&v16,  g_v);
    cudaGetSymbolAddress((void**)&wqkv, g_wqkv);
    cudaGetSymbolAddress((void**)&wo,   g_wo);
    cudaGetSymbolAddress((void**)&w1,   g_w1);
    cudaGetSymbolAddress((void**)&w2,   g_w2);

    cudaFuncSetAttribute(attn_hmma, cudaFuncAttributeMaxDynamicSharedMemorySize, ATT_SMEM);
    cudaFuncSetAttribute(gemm_hmma<1>, cudaFuncAttributeMaxDynamicSharedMemorySize, GEMM_SMEM);
    cudaFuncSetAttribute(gemm_hmma<2>, cudaFuncAttributeMaxDynamicSharedMemorySize, GEMM_SMEM);
    cudaFuncSetAttribute(gemm_hmma<3>, cudaFuncAttributeMaxDynamicSharedMemorySize, GEMM_SMEM);

    const dim3 blk(256);
    const dim3 wblk(32, 8);
    const dim3 gQKV(3*Dm / TNq, NTOK / TMq);  // (24, 64)
    const dim3 gP  (Dm   / TNq, NTOK / TMq);  // (8, 64)
    const dim3 gF1 (DFm  / TNq, NTOK / TMq);  // (32, 64)

    // 0) all weight converts + QKV bias concat in ONE launch
    wconv_all<<<12291, wblk>>>(Wq, Wk, Wv, Wo, W1, W2, bq, bk, bv,
                               wqkv, wo, w1, w2, bqkv);

    // 1) LN1 -> fp16
    ln_kernel<<<NTOK, blk>>>(x, ln1g, ln1b, a16);
    // 2) fused QKV projection -> fp16 scattered [B,H,S,64]; Q pre-scaled 1/8
    gemm_hmma<3><<<gQKV, blk, GEMM_SMEM>>>(a16, wqkv, bqkv, nullptr, nullptr,
                                           q16, k16, v16, 3*Dm, Dm);
    // 3) attention -> fp16 [B,S,D]
    attn_hmma<<<dim3(Sq / 128, Bq * Hh), blk, ATT_SMEM>>>(q16, k16, v16, a16);
    // 4) output projection + residual -> x2 (f32)
    gemm_hmma<2><<<gP, blk, GEMM_SMEM>>>(a16, wo, bo, x, x2,
                                         nullptr, nullptr, nullptr, Dm, Dm);
    // 5) LN2 -> fp16
    ln_kernel<<<NTOK, blk>>>(x2, ln2g, ln2b, a16);
    // 6) FFN up + exact GELU -> fp16
    gemm_hmma<1><<<gF1, blk, GEMM_SMEM>>>(a16, w1, b1, nullptr, nullptr,
                                          h16, nullptr, nullptr, DFm, Dm);
    // 7) FFN down + residual -> out (f32)
    gemm_hmma<2><<<gP, blk, GEMM_SMEM>>>(h16, w2, b2, x2, out,
                                         nullptr, nullptr, nullptr, Dm, DFm);
}